// round 5
// baseline (speedup 1.0000x reference)
#include <cuda_runtime.h>
#include <cuda_bf16.h>
#include <math.h>
#include <stdint.h>

// ---------------- problem constants ----------------
#define B_    32
#define FR_   300
#define D_    2048
#define ED_   4096      // E*D
#define G_    8
#define K_    64
#define FEAT_ 512       // E*D/G
#define VLAD_ 32768     // K*FEAT
#define H_    2048
#define HR_   256       // H/R
#define NC_   3862
#define M_    (B_*FR_)  // 9600
#define N2_   2400      // FR*G
#define BN_EPS 1e-5f
#define L2_EPS 1e-12f

// ---------------- scratch (device globals; no allocs allowed) ----------------
__device__ __align__(128) float g_rinv[M_];
__device__ __align__(128) float g_att[M_ * G_];
__device__ __align__(128) float g_act[M_ * (G_*K_)];
__device__ __align__(128) float g_actn[M_ * (G_*K_)];
__device__ __align__(128) float g_asum[B_ * K_];
__device__ __align__(128) float g_vlad[B_ * FEAT_ * K_];
__device__ __align__(128) float g_vladn[B_ * VLAD_];
__device__ __align__(128) float g_y0[B_ * H_];
__device__ __align__(128) float g_y[B_ * H_];
__device__ __align__(128) float g_z[B_ * HR_];
__device__ __align__(128) float g_yg[B_ * H_];
// bf16 hi/lo split buffers
__device__ __align__(128) __nv_bfloat16 g_xhi[M_ * D_];
__device__ __align__(128) __nv_bfloat16 g_xlo[M_ * D_];
__device__ __align__(128) __nv_bfloat16 g_whi[ED_ * D_];
__device__ __align__(128) __nv_bfloat16 g_wlo[ED_ * D_];
__device__ __align__(128) __nv_bfloat16 g_hhi[M_ * ED_];
__device__ __align__(128) __nv_bfloat16 g_hlo[M_ * ED_];
__device__ __align__(128) __nv_bfloat16 g_c1hi[(G_*K_) * ED_];
__device__ __align__(128) __nv_bfloat16 g_c1lo[(G_*K_) * ED_];

// ---------------- K1: per-row inverse L2 norm of x ----------------
__global__ void rownorm_inv_kernel(const float* __restrict__ x, float* __restrict__ rinv) {
    int m = blockIdx.x;
    int t = threadIdx.x;
    float s = 0.f;
    const float* row = x + (size_t)m * D_;
    for (int k = t; k < D_; k += 256) { float v = row[k]; s += v * v; }
    for (int o = 16; o; o >>= 1) s += __shfl_xor_sync(0xffffffffu, s, o);
    __shared__ float red[8];
    if ((t & 31) == 0) red[t >> 5] = s;
    __syncthreads();
    if (t == 0) {
        float tot = 0.f;
        #pragma unroll
        for (int i = 0; i < 8; i++) tot += red[i];
        rinv[m] = 1.f / fmaxf(sqrtf(tot), L2_EPS);
    }
}

// ---------------- K2: fp32 -> bf16 hi/lo split (optional per-row scale) ----------------
__global__ void split_kernel(const float* __restrict__ src,
                             __nv_bfloat16* __restrict__ hi, __nv_bfloat16* __restrict__ lo,
                             int n, const float* __restrict__ rowscale, int rowlen) {
    int i = (blockIdx.x * blockDim.x + threadIdx.x) * 4;
    if (i >= n) return;
    float4 v = *(const float4*)(src + i);
    if (rowscale) {
        float s = rowscale[i / rowlen];
        v.x *= s; v.y *= s; v.z *= s; v.w *= s;
    }
    __nv_bfloat16 h0 = __float2bfloat16(v.x), h1 = __float2bfloat16(v.y);
    __nv_bfloat16 h2 = __float2bfloat16(v.z), h3 = __float2bfloat16(v.w);
    __nv_bfloat162 a; a.x = h0; a.y = h1;
    __nv_bfloat162 b; b.x = h2; b.y = h3;
    *(__nv_bfloat162*)&hi[i]     = a;
    *(__nv_bfloat162*)&hi[i + 2] = b;
    a.x = __float2bfloat16(v.x - __bfloat162float(h0));
    a.y = __float2bfloat16(v.y - __bfloat162float(h1));
    b.x = __float2bfloat16(v.z - __bfloat162float(h2));
    b.y = __float2bfloat16(v.w - __bfloat162float(h3));
    *(__nv_bfloat162*)&lo[i]     = a;
    *(__nv_bfloat162*)&lo[i + 2] = b;
}

// ---------------- K2b: fused transpose + split: c1[R,C] -> c1hi/lo[C,R] ----------------
__global__ void transpose_split_kernel(const float* __restrict__ in,
                                       __nv_bfloat16* __restrict__ hi,
                                       __nv_bfloat16* __restrict__ lo, int R, int C) {
    __shared__ float tile[32][33];
    int c0 = blockIdx.x * 32, r0 = blockIdx.y * 32;
    int tx = threadIdx.x & 31, ty = threadIdx.x >> 5;   // 256 thr
    #pragma unroll
    for (int i = 0; i < 32; i += 8)
        tile[ty + i][tx] = in[(size_t)(r0 + ty + i) * C + c0 + tx];
    __syncthreads();
    #pragma unroll
    for (int i = 0; i < 32; i += 8) {
        float v = tile[tx][ty + i];
        __nv_bfloat16 hv = __float2bfloat16(v);
        size_t idx = (size_t)(c0 + ty + i) * R + r0 + tx;
        hi[idx] = hv;
        lo[idx] = __float2bfloat16(v - __bfloat162float(hv));
    }
}

// ---------------- tensor-core GEMM: C[M,N] = A[M,K] * B[N,K]^T  (bf16 split, fp32 acc) ----
#define BM 128
#define BN 128
#define BKK 64
#define SSTRIDE 72                        // BKK + 8 (bank-conflict-free ldmatrix)
#define MAT_BYTES (128 * SSTRIDE * 2)     // 18432
#define STAGE_BYTES (4 * MAT_BYTES)       // 73728
#define NSTAGE 3
#define GEMM_SMEM (NSTAGE * STAGE_BYTES)  // 221184

__device__ __forceinline__ void cp16(uint32_t dst, const void* src) {
    asm volatile("cp.async.cg.shared.global [%0], [%1], 16;\n" :: "r"(dst), "l"(src));
}
__device__ __forceinline__ void ldsm_x4(uint32_t& r0, uint32_t& r1, uint32_t& r2, uint32_t& r3,
                                        uint32_t addr) {
    asm volatile("ldmatrix.sync.aligned.m8n8.x4.shared.b16 {%0,%1,%2,%3}, [%4];\n"
                 : "=r"(r0), "=r"(r1), "=r"(r2), "=r"(r3) : "r"(addr));
}
__device__ __forceinline__ void mma16816(float* c, const uint32_t* a, const uint32_t* b) {
    asm volatile("mma.sync.aligned.m16n8k16.row.col.f32.bf16.bf16.f32 "
                 "{%0,%1,%2,%3},{%4,%5,%6,%7},{%8,%9},{%0,%1,%2,%3};\n"
                 : "+f"(c[0]), "+f"(c[1]), "+f"(c[2]), "+f"(c[3])
                 : "r"(a[0]), "r"(a[1]), "r"(a[2]), "r"(a[3]), "r"(b[0]), "r"(b[1]));
}

// MODE 0: emit Chi/Clo = bf16 split of (acc + p0[n])   (no fp32 C)
// MODE 1: emit C fp32 = (acc - p2[n])*rsqrt(p3[n]+eps)*p0[n] + p1[n]
template <int MODE>
__global__ __launch_bounds__(256, 1)
void mma_gemm_kernel(const __nv_bfloat16* __restrict__ Ahi, const __nv_bfloat16* __restrict__ Alo,
                     const __nv_bfloat16* __restrict__ Bhi, const __nv_bfloat16* __restrict__ Blo,
                     float* __restrict__ C, __nv_bfloat16* __restrict__ Chi,
                     __nv_bfloat16* __restrict__ Clo, int M, int N, int K,
                     const float* __restrict__ p0, const float* __restrict__ p1,
                     const float* __restrict__ p2, const float* __restrict__ p3) {
    extern __shared__ __align__(16) unsigned char smem_raw[];
    uint32_t sbase = (uint32_t)__cvta_generic_to_shared(smem_raw);

    const int t = threadIdx.x;
    const int lane = t & 31;
    const int warp = t >> 5;
    const int wy = warp >> 2;       // 0..1 (M)
    const int wx = warp & 3;        // 0..3 (N)
    const int m0 = blockIdx.y * BM;
    const int n0 = blockIdx.x * BN;

    float acc[4][4][4];
    #pragma unroll
    for (int i = 0; i < 4; i++)
        #pragma unroll
        for (int j = 0; j < 4; j++)
            #pragma unroll
            for (int q = 0; q < 4; q++) acc[i][j][q] = 0.f;

    auto issue = [&](int chunk, int buf) {
        uint32_t sb = sbase + buf * STAGE_BYTES;
        int kpos = chunk * BKK;
        #pragma unroll
        for (int i = 0; i < 4; i++) {
            int c = t + i * 256;
            int row = c >> 3, seg = c & 7;
            uint32_t so = (uint32_t)(row * SSTRIDE + seg * 8) * 2;
            size_t ga = (size_t)(m0 + row) * K + kpos + seg * 8;
            size_t gb = (size_t)(n0 + row) * K + kpos + seg * 8;
            cp16(sb + 0 * MAT_BYTES + so, Ahi + ga);
            cp16(sb + 1 * MAT_BYTES + so, Alo + ga);
            cp16(sb + 2 * MAT_BYTES + so, Bhi + gb);
            cp16(sb + 3 * MAT_BYTES + so, Blo + gb);
        }
        asm volatile("cp.async.commit_group;\n");
    };

    // per-thread fragment address offsets (bytes, within a matrix)
    const uint32_t aOff = (uint32_t)((wy * 64 + (lane & 15)) * SSTRIDE + ((lane >> 4) * 8)) * 2;
    const uint32_t bOff = (uint32_t)((wx * 32 + ((lane >> 4) * 8) + (lane & 7)) * SSTRIDE
                                     + (((lane >> 3) & 1) * 8)) * 2;

    const int NK = K / BKK;
    int issued = 0;
    #pragma unroll
    for (int p = 0; p < NSTAGE; p++) {
        if (issued < NK) { issue(issued, issued % NSTAGE); issued++; }
    }

    for (int kt = 0; kt < NK; kt++) {
        int rem = issued - kt - 1;   // groups allowed to stay pending
        if (rem >= 2)      asm volatile("cp.async.wait_group 2;\n" ::: "memory");
        else if (rem == 1) asm volatile("cp.async.wait_group 1;\n" ::: "memory");
        else               asm volatile("cp.async.wait_group 0;\n" ::: "memory");
        __syncthreads();
        uint32_t sb = sbase + (kt % NSTAGE) * STAGE_BYTES;
        #pragma unroll
        for (int kk = 0; kk < BKK / 16; kk++) {
            uint32_t kby = (uint32_t)(kk * 16) * 2;
            uint32_t ahi[4][4], alo[4][4], bhi[4][2], blo[4][2];
            #pragma unroll
            for (int mt = 0; mt < 4; mt++) {
                uint32_t ad = sb + aOff + kby + (uint32_t)(mt * 16 * SSTRIDE) * 2;
                ldsm_x4(ahi[mt][0], ahi[mt][1], ahi[mt][2], ahi[mt][3], ad);
                ldsm_x4(alo[mt][0], alo[mt][1], alo[mt][2], alo[mt][3], ad + MAT_BYTES);
            }
            #pragma unroll
            for (int p = 0; p < 2; p++) {
                uint32_t bd = sb + 2 * MAT_BYTES + bOff + kby + (uint32_t)(p * 16 * SSTRIDE) * 2;
                uint32_t r0, r1, r2, r3;
                ldsm_x4(r0, r1, r2, r3, bd);
                bhi[p * 2][0] = r0; bhi[p * 2][1] = r1;
                bhi[p * 2 + 1][0] = r2; bhi[p * 2 + 1][1] = r3;
                ldsm_x4(r0, r1, r2, r3, bd + MAT_BYTES);
                blo[p * 2][0] = r0; blo[p * 2][1] = r1;
                blo[p * 2 + 1][0] = r2; blo[p * 2 + 1][1] = r3;
            }
            #pragma unroll
            for (int mt = 0; mt < 4; mt++)
                #pragma unroll
                for (int nt = 0; nt < 4; nt++) {
                    mma16816(acc[mt][nt], ahi[mt], bhi[nt]);
                    mma16816(acc[mt][nt], ahi[mt], blo[nt]);
                    mma16816(acc[mt][nt], alo[mt], bhi[nt]);
                }
        }
        __syncthreads();
        if (issued < NK) { issue(issued, issued % NSTAGE); issued++; }
    }

    // epilogue
    #pragma unroll
    for (int mt = 0; mt < 4; mt++) {
        int r = m0 + wy * 64 + mt * 16 + (lane >> 2);
        #pragma unroll
        for (int nt = 0; nt < 4; nt++) {
            int c = n0 + wx * 32 + nt * 8 + (lane & 3) * 2;
            float v00 = acc[mt][nt][0], v01 = acc[mt][nt][1];
            float v10 = acc[mt][nt][2], v11 = acc[mt][nt][3];
            if (MODE == 0) {
                float b0 = p0[c], b1 = p0[c + 1];
                v00 += b0; v01 += b1; v10 += b0; v11 += b1;
                __nv_bfloat16 h00 = __float2bfloat16(v00), h01 = __float2bfloat16(v01);
                __nv_bfloat16 h10 = __float2bfloat16(v10), h11 = __float2bfloat16(v11);
                __nv_bfloat162 hh;
                hh.x = h00; hh.y = h01; *(__nv_bfloat162*)&Chi[(size_t)r * N + c] = hh;
                hh.x = h10; hh.y = h11; *(__nv_bfloat162*)&Chi[(size_t)(r + 8) * N + c] = hh;
                __nv_bfloat162 ll;
                ll.x = __float2bfloat16(v00 - __bfloat162float(h00));
                ll.y = __float2bfloat16(v01 - __bfloat162float(h01));
                *(__nv_bfloat162*)&Clo[(size_t)r * N + c] = ll;
                ll.x = __float2bfloat16(v10 - __bfloat162float(h10));
                ll.y = __float2bfloat16(v11 - __bfloat162float(h11));
                *(__nv_bfloat162*)&Clo[(size_t)(r + 8) * N + c] = ll;
            } else {
                float s0 = rsqrtf(p3[c] + BN_EPS) * p0[c];
                float s1 = rsqrtf(p3[c + 1] + BN_EPS) * p0[c + 1];
                float t0 = p1[c] - p2[c] * s0;
                float t1 = p1[c + 1] - p2[c + 1] * s1;
                float2 o0 = {v00 * s0 + t0, v01 * s1 + t1};
                float2 o1 = {v10 * s0 + t0, v11 * s1 + t1};
                *(float2*)&C[(size_t)r * N + c] = o0;
                *(float2*)&C[(size_t)(r + 8) * N + c] = o1;
            }
        }
    }
}

// ---------------- K3: attention = sigmoid(h @ fc2_w^T + b), h = hi + lo ----------------
__global__ void att_kernel(const __nv_bfloat16* __restrict__ hhi,
                           const __nv_bfloat16* __restrict__ hlo,
                           const float* __restrict__ w2,
                           const float* __restrict__ b2, float* __restrict__ att) {
    int m = blockIdx.x;
    int warp = threadIdx.x >> 5, lane = threadIdx.x & 31;
    const __nv_bfloat16* hr = hhi + (size_t)m * ED_;
    const __nv_bfloat16* lr = hlo + (size_t)m * ED_;
    const float* wr = w2 + (size_t)warp * ED_;
    float s = 0.f;
    for (int k = lane; k < ED_; k += 32)
        s += (__bfloat162float(hr[k]) + __bfloat162float(lr[k])) * wr[k];
    for (int o = 16; o; o >>= 1) s += __shfl_xor_sync(0xffffffffu, s, o);
    if (lane == 0) {
        float v = s + b2[warp];
        att[m * G_ + warp] = 1.f / (1.f + expf(-v));
    }
}

// ---------------- K6: softmax over K within each group, times attention ----------------
__global__ void softmax_att_kernel(const float* __restrict__ act, const float* __restrict__ att,
                                   float* __restrict__ actn) {
    int m = blockIdx.x;
    int g = threadIdx.x >> 5, lane = threadIdx.x & 31;
    const float* row = act + (size_t)m * (G_ * K_) + g * K_;
    float v0 = row[lane], v1 = row[lane + 32];
    float mx = fmaxf(v0, v1);
    for (int o = 16; o; o >>= 1) mx = fmaxf(mx, __shfl_xor_sync(0xffffffffu, mx, o));
    float e0 = expf(v0 - mx), e1 = expf(v1 - mx);
    float s = e0 + e1;
    for (int o = 16; o; o >>= 1) s += __shfl_xor_sync(0xffffffffu, s, o);
    float scl = att[m * G_ + g] / s;
    float* orow = actn + (size_t)m * (G_ * K_) + g * K_;
    orow[lane] = e0 * scl;
    orow[lane + 32] = e1 * scl;
}

// ---------------- K7: asum[b,k] ----------------
__global__ void asum_kernel(const float* __restrict__ actn, float* __restrict__ asum) {
    int b = blockIdx.x;
    int t = threadIdx.x;
    int k = t & 63, grp = t >> 6;
    float s = 0.f;
    for (int n = grp; n < N2_; n += 4) {
        int row = b * FR_ + (n >> 3);
        s += actn[(size_t)row * (G_ * K_) + (n & 7) * K_ + k];
    }
    __shared__ float red[256];
    red[t] = s;
    __syncthreads();
    if (grp == 0) {
        float tot = red[k] + red[64 + k] + red[128 + k] + red[192 + k];
        asum[b * K_ + k] = tot;
    }
}

// ---------------- K8: batched VLAD GEMM, h = hi + lo ----------------
__global__ void vlad_gemm_kernel(const __nv_bfloat16* __restrict__ hhi,
                                 const __nv_bfloat16* __restrict__ hlo,
                                 const float* __restrict__ actn,
                                 const float* __restrict__ asum, const float* __restrict__ c2,
                                 float* __restrict__ vlad) {
    int b  = blockIdx.x;
    int f0 = blockIdx.y * 64;
    __shared__ float Rs[32][68];
    __shared__ float Qs[32][68];
    int t = threadIdx.x;
    int tx = t & 15, ty = t >> 4;
    float acc[4][4];
    #pragma unroll
    for (int i = 0; i < 4; i++)
        #pragma unroll
        for (int j = 0; j < 4; j++) acc[i][j] = 0.f;

    for (int n0 = 0; n0 < N2_; n0 += 32) {
        __syncthreads();
        #pragma unroll
        for (int i = 0; i < 8; i++) {
            int idx = t + i * 256;
            int n = idx >> 6, f = idx & 63;
            int nn = n0 + n;
            int row = b * FR_ + (nn >> 3);
            size_t hidx = (size_t)row * ED_ + (nn & 7) * FEAT_ + f0 + f;
            Rs[n][f] = __bfloat162float(hhi[hidx]) + __bfloat162float(hlo[hidx]);
            Qs[n][f] = actn[(size_t)row * (G_ * K_) + (nn & 7) * K_ + f];
        }
        __syncthreads();
        #pragma unroll
        for (int nn = 0; nn < 32; nn++) {
            float rf[4], qf[4];
            *(float4*)rf = *(const float4*)&Rs[nn][ty * 4];
            *(float4*)qf = *(const float4*)&Qs[nn][tx * 4];
            #pragma unroll
            for (int i = 0; i < 4; i++)
                #pragma unroll
                for (int j = 0; j < 4; j++) acc[i][j] += rf[i] * qf[j];
        }
    }
    #pragma unroll
    for (int i = 0; i < 4; i++) {
        int f = f0 + ty * 4 + i;
        #pragma unroll
        for (int j = 0; j < 4; j++) {
            int k = tx * 4 + j;
            float v = acc[i][j] - asum[b * K_ + k] * c2[(size_t)f * K_ + k];
            vlad[((size_t)b * FEAT_ + f) * K_ + k] = v;
        }
    }
}

// ---------------- K9: intra-norm + BN2 ----------------
__global__ void intranorm_bn_kernel(const float* __restrict__ vlad, float* __restrict__ vladn,
                                    const float* __restrict__ g, const float* __restrict__ bb,
                                    const float* __restrict__ mm, const float* __restrict__ vv) {
    int b = blockIdx.x;
    int t = threadIdx.x;
    int k = t & 63, fg = t >> 6;
    float s = 0.f;
    for (int f = fg; f < FEAT_; f += 8) {
        float x = vlad[((size_t)b * FEAT_ + f) * K_ + k];
        s += x * x;
    }
    __shared__ float red[512];
    red[t] = s;
    __syncthreads();
    if (fg == 0) {
        float tot = 0.f;
        #pragma unroll
        for (int i = 0; i < 8; i++) tot += red[i * 64 + k];
        red[k] = 1.f / fmaxf(sqrtf(tot), L2_EPS);
    }
    __syncthreads();
    float inv = red[k];
    for (int f = fg; f < FEAT_; f += 8) {
        int idx = f * K_ + k;
        float x = vlad[((size_t)b * FEAT_ + f) * K_ + k] * inv;
        vladn[(size_t)b * VLAD_ + idx] =
            (x - mm[idx]) * rsqrtf(vv[idx] + BN_EPS) * g[idx] + bb[idx];
    }
}

// ---------------- K10: broadcast bias init ----------------
__global__ void bias_init_kernel(float* __restrict__ C, const float* __restrict__ bias,
                                 int rows, int N) {
    int idx = blockIdx.x * blockDim.x + threadIdx.x;
    if (idx < rows * N) C[idx] = bias[idx % N];
}

// ---------------- K11: skinny GEMM (split-K, atomic) ----------------
__global__ void skinny32_kernel(const float* __restrict__ A, const float* __restrict__ W,
                                float* __restrict__ C, int N, int K, int KC) {
    int o0 = blockIdx.x * 128;
    int k0 = blockIdx.y * KC;
    __shared__ float As[32][36];
    __shared__ float Ws[32][132];
    int t = threadIdx.x;
    int kl = t & 31, rg = t >> 5;
    int oq = t & 31, bq = t >> 5;
    float acc[4][4];
    #pragma unroll
    for (int i = 0; i < 4; i++)
        #pragma unroll
        for (int j = 0; j < 4; j++) acc[i][j] = 0.f;

    int kend = min(k0 + KC, K);
    for (int kt = k0; kt < kend; kt += 32) {
        __syncthreads();
        #pragma unroll
        for (int i = 0; i < 4; i++) {
            int b = rg + i * 8;
            As[kl][b] = A[(size_t)b * K + kt + kl];
        }
        #pragma unroll
        for (int i = 0; i < 16; i++) {
            int o = rg + i * 8;
            int og = o0 + o;
            Ws[kl][o] = (og < N) ? W[(size_t)og * K + kt + kl] : 0.f;
        }
        __syncthreads();
        #pragma unroll
        for (int kk = 0; kk < 32; kk++) {
            float4 w4 = *(const float4*)&Ws[kk][oq * 4];
            float4 a4 = *(const float4*)&As[kk][bq * 4];
            float av[4] = {a4.x, a4.y, a4.z, a4.w};
            float wv[4] = {w4.x, w4.y, w4.z, w4.w};
            #pragma unroll
            for (int i = 0; i < 4; i++)
                #pragma unroll
                for (int j = 0; j < 4; j++) acc[i][j] += av[i] * wv[j];
        }
    }
    #pragma unroll
    for (int i = 0; i < 4; i++) {
        int b = bq * 4 + i;
        #pragma unroll
        for (int j = 0; j < 4; j++) {
            int o = o0 + oq * 4 + j;
            if (o < N) atomicAdd(&C[(size_t)b * N + o], acc[i][j]);
        }
    }
}

// ---------------- K12: BN ----------------
__global__ void bn_kernel(const float* __restrict__ in, float* __restrict__ out,
                          const float* __restrict__ g, const float* __restrict__ bb,
                          const float* __restrict__ mm, const float* __restrict__ vv,
                          int rows, int N) {
    int idx = blockIdx.x * blockDim.x + threadIdx.x;
    if (idx < rows * N) {
        int c = idx % N;
        out[idx] = (in[idx] - mm[c]) * rsqrtf(vv[c] + BN_EPS) * g[c] + bb[c];
    }
}

// ---------------- K13/K14: SE gating ----------------
__global__ void se1_kernel(const float* __restrict__ y, const float* __restrict__ w,
                           const float* __restrict__ bias,
                           const float* __restrict__ g, const float* __restrict__ bb,
                           const float* __restrict__ mm, const float* __restrict__ vv,
                           float* __restrict__ z) {
    int warp = threadIdx.x >> 5, lane = threadIdx.x & 31;
    int idx = blockIdx.x * 8 + warp;
    int b = idx / HR_, o = idx % HR_;
    const float* yr = y + (size_t)b * H_;
    const float* wr = w + (size_t)o * H_;
    float s = 0.f;
    for (int k = lane; k < H_; k += 32) s += yr[k] * wr[k];
    for (int off = 16; off; off >>= 1) s += __shfl_xor_sync(0xffffffffu, s, off);
    if (lane == 0) {
        float v = s + bias[o];
        v = (v - mm[o]) * rsqrtf(vv[o] + BN_EPS) * g[o] + bb[o];
        z[(size_t)b * HR_ + o] = fmaxf(v, 0.f);
    }
}

__global__ void se2_kernel(const float* __restrict__ z, const float* __restrict__ w,
                           const float* __restrict__ bias, const float* __restrict__ y,
                           float* __restrict__ yg) {
    int warp = threadIdx.x >> 5, lane = threadIdx.x & 31;
    int idx = blockIdx.x * 8 + warp;
    int b = idx / H_, o = idx % H_;
    const float* zr = z + (size_t)b * HR_;
    const float* wr = w + (size_t)o * HR_;
    float s = 0.f;
    for (int k = lane; k < HR_; k += 32) s += zr[k] * wr[k];
    for (int off = 16; off; off >>= 1) s += __shfl_xor_sync(0xffffffffu, s, off);
    if (lane == 0) {
        float gate = 1.f / (1.f + expf(-(s + bias[o])));
        yg[(size_t)b * H_ + o] = y[(size_t)b * H_ + o] * gate;
    }
}

// ---------------- host launcher ----------------
extern "C" void kernel_launch(void* const* d_in, const int* in_sizes, int n_in,
                              void* d_out, int out_size) {
    const float* x     = (const float*)d_in[0];
    const float* fc1_w = (const float*)d_in[1];
    const float* fc1_b = (const float*)d_in[2];
    const float* fc2_w = (const float*)d_in[3];
    const float* fc2_b = (const float*)d_in[4];
    const float* c1    = (const float*)d_in[5];
    const float* c2    = (const float*)d_in[6];
    const float* bn1_g = (const float*)d_in[7];
    const float* bn1_b = (const float*)d_in[8];
    const float* bn1_m = (const float*)d_in[9];
    const float* bn1_v = (const float*)d_in[10];
    const float* bn2_g = (const float*)d_in[11];
    const float* bn2_b = (const float*)d_in[12];
    const float* bn2_m = (const float*)d_in[13];
    const float* bn2_v = (const float*)d_in[14];
    const float* cgf_w = (const float*)d_in[15];
    const float* cgf_b = (const float*)d_in[16];
    const float* cgbn_g = (const float*)d_in[17];
    const float* cgbn_b = (const float*)d_in[18];
    const float* cgbn_m = (const float*)d_in[19];
    const float* cgbn_v = (const float*)d_in[20];
    const float* g1_w  = (const float*)d_in[21];
    const float* g1_b  = (const float*)d_in[22];
    const float* gbn_g = (const float*)d_in[23];
    const float* gbn_b = (const float*)d_in[24];
    const float* gbn_m = (const float*)d_in[25];
    const float* gbn_v = (const float*)d_in[26];
    const float* g2_w  = (const float*)d_in[27];
    const float* g2_b  = (const float*)d_in[28];
    const float* fc3_w = (const float*)d_in[29];
    const float* fc3_b = (const float*)d_in[30];
    float* out = (float*)d_out;

    float *rinv, *att, *act, *actn, *asum, *vlad, *vladn, *y0, *y, *z, *yg;
    __nv_bfloat16 *xhi, *xlo, *whi, *wlo, *hhi, *hlo, *c1hi, *c1lo;
    cudaGetSymbolAddress((void**)&rinv,  g_rinv);
    cudaGetSymbolAddress((void**)&att,   g_att);
    cudaGetSymbolAddress((void**)&act,   g_act);
    cudaGetSymbolAddress((void**)&actn,  g_actn);
    cudaGetSymbolAddress((void**)&asum,  g_asum);
    cudaGetSymbolAddress((void**)&vlad,  g_vlad);
    cudaGetSymbolAddress((void**)&vladn, g_vladn);
    cudaGetSymbolAddress((void**)&y0,    g_y0);
    cudaGetSymbolAddress((void**)&y,     g_y);
    cudaGetSymbolAddress((void**)&z,     g_z);
    cudaGetSymbolAddress((void**)&yg,    g_yg);
    cudaGetSymbolAddress((void**)&xhi,   g_xhi);
    cudaGetSymbolAddress((void**)&xlo,   g_xlo);
    cudaGetSymbolAddress((void**)&whi,   g_whi);
    cudaGetSymbolAddress((void**)&wlo,   g_wlo);
    cudaGetSymbolAddress((void**)&hhi,   g_hhi);
    cudaGetSymbolAddress((void**)&hlo,   g_hlo);
    cudaGetSymbolAddress((void**)&c1hi,  g_c1hi);
    cudaGetSymbolAddress((void**)&c1lo,  g_c1lo);

    cudaFuncSetAttribute(mma_gemm_kernel<0>, cudaFuncAttributeMaxDynamicSharedMemorySize, GEMM_SMEM);
    cudaFuncSetAttribute(mma_gemm_kernel<1>, cudaFuncAttributeMaxDynamicSharedMemorySize, GEMM_SMEM);

    // 1. row inverse norms of x
    rownorm_inv_kernel<<<M_, 256>>>(x, rinv);

    // 2. split x (scaled by rinv) and fc1_w into bf16 hi/lo
    split_kernel<<<(M_ * D_ / 4 + 255) / 256, 256>>>(x, xhi, xlo, M_ * D_, rinv, D_);
    split_kernel<<<(ED_ * D_ / 4 + 255) / 256, 256>>>(fc1_w, whi, wlo, ED_ * D_, nullptr, 0);

    // 3. h (bf16 hi/lo only) = xn @ fc1_w^T + fc1_b — tensor cores
    mma_gemm_kernel<0><<<dim3(ED_ / BN, M_ / BM), 256, GEMM_SMEM>>>(
        xhi, xlo, whi, wlo, nullptr, hhi, hlo, M_, ED_, D_, fc1_b, nullptr, nullptr, nullptr);

    // 4. attention
    att_kernel<<<M_, 256>>>(hhi, hlo, fc2_w, fc2_b, att);

    // 5. c1^T + split, fused
    transpose_split_kernel<<<dim3((G_ * K_) / 32, ED_ / 32), 256>>>(c1, c1hi, c1lo, ED_, G_ * K_);

    // 6. act = BN1(h @ c1) — tensor cores
    mma_gemm_kernel<1><<<dim3((G_ * K_) / BN, M_ / BM), 256, GEMM_SMEM>>>(
        hhi, hlo, c1hi, c1lo, act, nullptr, nullptr, M_, G_ * K_, ED_,
        bn1_g, bn1_b, bn1_m, bn1_v);

    // 7. softmax * att
    softmax_att_kernel<<<M_, 256>>>(act, att, actn);

    // 8. asum
    asum_kernel<<<B_, 256>>>(actn, asum);

    // 9. vlad
    vlad_gemm_kernel<<<dim3(B_, FEAT_ / 64), 256>>>(hhi, hlo, actn, asum, c2, vlad);

    // 10. intra-norm + BN2
    intranorm_bn_kernel<<<B_, 512>>>(vlad, vladn, bn2_g, bn2_b, bn2_m, bn2_v);

    // 11. y = BN(vladn @ cgf_w^T + cgf_b)
    bias_init_kernel<<<(B_ * H_ + 255) / 256, 256>>>(y0, cgf_b, B_, H_);
    skinny32_kernel<<<dim3(H_ / 128, 16), 256>>>(vladn, cgf_w, y0, H_, VLAD_, VLAD_ / 16);
    bn_kernel<<<(B_ * H_ + 255) / 256, 256>>>(y0, y, cgbn_g, cgbn_b, cgbn_m, cgbn_v, B_, H_);

    // 12. SE gating
    se1_kernel<<<(B_ * HR_) / 8, 256>>>(y, g1_w, g1_b, gbn_g, gbn_b, gbn_m, gbn_v, z);
    se2_kernel<<<(B_ * H_) / 8, 256>>>(z, g2_w, g2_b, y, yg);

    // 13. out = yg @ fc3_w^T + fc3_b
    bias_init_kernel<<<(B_ * NC_ + 255) / 256, 256>>>(out, fc3_b, B_, NC_);
    skinny32_kernel<<<dim3((NC_ + 127) / 128, 8), 256>>>(yg, fc3_w, out, NC_, H_, H_ / 8);
}

// round 6
// speedup vs baseline: 1.0333x; 1.0333x over previous
#include <cuda_runtime.h>
#include <cuda_bf16.h>
#include <math.h>
#include <stdint.h>

// ---------------- problem constants ----------------
#define B_    32
#define FR_   300
#define D_    2048
#define ED_   4096      // E*D
#define G_    8
#define K_    64
#define FEAT_ 512       // E*D/G
#define VLAD_ 32768     // K*FEAT
#define H_    2048
#define HR_   256       // H/R
#define NC_   3862
#define M_    (B_*FR_)  // 9600
#define N2_   2400      // FR*G
#define BN_EPS 1e-5f
#define L2_EPS 1e-12f

// ---------------- scratch (device globals; no allocs allowed) ----------------
__device__ __align__(128) float g_rinv[M_];
__device__ __align__(128) float g_att[M_ * G_];
__device__ __align__(128) float g_act[M_ * (G_*K_)];
__device__ __align__(128) float g_actn[M_ * (G_*K_)];
__device__ __align__(128) float g_asum[B_ * K_];
__device__ __align__(128) float g_vlad[B_ * FEAT_ * K_];
__device__ __align__(128) float g_vladn[B_ * VLAD_];
__device__ __align__(128) float g_y0[B_ * H_];
__device__ __align__(128) float g_y[B_ * H_];
__device__ __align__(128) float g_z[B_ * HR_];
__device__ __align__(128) float g_yg[B_ * H_];
// bf16 hi/lo split buffers
__device__ __align__(128) __nv_bfloat16 g_xhi[M_ * D_];
__device__ __align__(128) __nv_bfloat16 g_xlo[M_ * D_];
__device__ __align__(128) __nv_bfloat16 g_whi[ED_ * D_];
__device__ __align__(128) __nv_bfloat16 g_wlo[ED_ * D_];
__device__ __align__(128) __nv_bfloat16 g_hhi[M_ * ED_];
__device__ __align__(128) __nv_bfloat16 g_hlo[M_ * ED_];
__device__ __align__(128) __nv_bfloat16 g_c1hi[(G_*K_) * ED_];
__device__ __align__(128) __nv_bfloat16 g_c1lo[(G_*K_) * ED_];

// ---------------- K1: per-row inverse L2 norm of x ----------------
__global__ void rownorm_inv_kernel(const float* __restrict__ x, float* __restrict__ rinv) {
    int m = blockIdx.x;
    int t = threadIdx.x;
    float s = 0.f;
    const float* row = x + (size_t)m * D_;
    for (int k = t; k < D_; k += 256) { float v = row[k]; s += v * v; }
    for (int o = 16; o; o >>= 1) s += __shfl_xor_sync(0xffffffffu, s, o);
    __shared__ float red[8];
    if ((t & 31) == 0) red[t >> 5] = s;
    __syncthreads();
    if (t == 0) {
        float tot = 0.f;
        #pragma unroll
        for (int i = 0; i < 8; i++) tot += red[i];
        rinv[m] = 1.f / fmaxf(sqrtf(tot), L2_EPS);
    }
}

// ---------------- K2: fp32 -> bf16 hi/lo split (optional per-row scale) ----------------
__global__ void split_kernel(const float* __restrict__ src,
                             __nv_bfloat16* __restrict__ hi, __nv_bfloat16* __restrict__ lo,
                             int n, const float* __restrict__ rowscale, int rowlen) {
    int i = (blockIdx.x * blockDim.x + threadIdx.x) * 4;
    if (i >= n) return;
    float4 v = *(const float4*)(src + i);
    if (rowscale) {
        float s = rowscale[i / rowlen];
        v.x *= s; v.y *= s; v.z *= s; v.w *= s;
    }
    __nv_bfloat16 h0 = __float2bfloat16(v.x), h1 = __float2bfloat16(v.y);
    __nv_bfloat16 h2 = __float2bfloat16(v.z), h3 = __float2bfloat16(v.w);
    __nv_bfloat162 a; a.x = h0; a.y = h1;
    __nv_bfloat162 b; b.x = h2; b.y = h3;
    *(__nv_bfloat162*)&hi[i]     = a;
    *(__nv_bfloat162*)&hi[i + 2] = b;
    a.x = __float2bfloat16(v.x - __bfloat162float(h0));
    a.y = __float2bfloat16(v.y - __bfloat162float(h1));
    b.x = __float2bfloat16(v.z - __bfloat162float(h2));
    b.y = __float2bfloat16(v.w - __bfloat162float(h3));
    *(__nv_bfloat162*)&lo[i]     = a;
    *(__nv_bfloat162*)&lo[i + 2] = b;
}

// ---------------- K2b: fused transpose + split: c1[R,C] -> c1hi/lo[C,R] ----------------
__global__ void transpose_split_kernel(const float* __restrict__ in,
                                       __nv_bfloat16* __restrict__ hi,
                                       __nv_bfloat16* __restrict__ lo, int R, int C) {
    __shared__ float tile[32][33];
    int c0 = blockIdx.x * 32, r0 = blockIdx.y * 32;
    int tx = threadIdx.x & 31, ty = threadIdx.x >> 5;   // 256 thr
    #pragma unroll
    for (int i = 0; i < 32; i += 8)
        tile[ty + i][tx] = in[(size_t)(r0 + ty + i) * C + c0 + tx];
    __syncthreads();
    #pragma unroll
    for (int i = 0; i < 32; i += 8) {
        float v = tile[tx][ty + i];
        __nv_bfloat16 hv = __float2bfloat16(v);
        size_t idx = (size_t)(c0 + ty + i) * R + r0 + tx;
        hi[idx] = hv;
        lo[idx] = __float2bfloat16(v - __bfloat162float(hv));
    }
}

// ---------------- tensor-core GEMM: C[M,N] = A[M,K] * B[N,K]^T  (bf16 split, fp32 acc) ----
#define BM 128
#define BN 128
#define BKK 64
#define SSTRIDE 72                        // BKK + 8 (bank-conflict-free ldmatrix)
#define MAT_BYTES (128 * SSTRIDE * 2)     // 18432
#define STAGE_BYTES (4 * MAT_BYTES)       // 73728
#define NSTAGE 3
#define GEMM_SMEM (NSTAGE * STAGE_BYTES)  // 221184

__device__ __forceinline__ void cp16(uint32_t dst, const void* src) {
    asm volatile("cp.async.cg.shared.global [%0], [%1], 16;\n" :: "r"(dst), "l"(src));
}
__device__ __forceinline__ void ldsm_x4(uint32_t& r0, uint32_t& r1, uint32_t& r2, uint32_t& r3,
                                        uint32_t addr) {
    asm volatile("ldmatrix.sync.aligned.m8n8.x4.shared.b16 {%0,%1,%2,%3}, [%4];\n"
                 : "=r"(r0), "=r"(r1), "=r"(r2), "=r"(r3) : "r"(addr));
}
__device__ __forceinline__ void mma16816(float* c, const uint32_t* a, const uint32_t* b) {
    asm volatile("mma.sync.aligned.m16n8k16.row.col.f32.bf16.bf16.f32 "
                 "{%0,%1,%2,%3},{%4,%5,%6,%7},{%8,%9},{%0,%1,%2,%3};\n"
                 : "+f"(c[0]), "+f"(c[1]), "+f"(c[2]), "+f"(c[3])
                 : "r"(a[0]), "r"(a[1]), "r"(a[2]), "r"(a[3]), "r"(b[0]), "r"(b[1]));
}

// MODE 0: emit Chi/Clo = bf16 split of (acc + p0[n])   (no fp32 C)
// MODE 1: emit C fp32 = (acc - p2[n])*rsqrt(p3[n]+eps)*p0[n] + p1[n]
template <int MODE>
__global__ __launch_bounds__(256)
void mma_gemm_kernel(const __nv_bfloat16* __restrict__ Ahi, const __nv_bfloat16* __restrict__ Alo,
                     const __nv_bfloat16* __restrict__ Bhi, const __nv_bfloat16* __restrict__ Blo,
                     float* __restrict__ C, __nv_bfloat16* __restrict__ Chi,
                     __nv_bfloat16* __restrict__ Clo, int M, int N, int K,
                     const float* __restrict__ p0, const float* __restrict__ p1,
                     const float* __restrict__ p2, const float* __restrict__ p3) {
    extern __shared__ __align__(16) unsigned char smem_raw[];
    uint32_t sbase = (uint32_t)__cvta_generic_to_shared(smem_raw);

    const int t = threadIdx.x;
    const int lane = t & 31;
    const int warp = t >> 5;
    const int wy = warp >> 2;       // 0..1 (M)
    const int wx = warp & 3;        // 0..3 (N)
    const int m0 = blockIdx.y * BM;
    const int n0 = blockIdx.x * BN;

    float acc[4][4][4];
    #pragma unroll
    for (int i = 0; i < 4; i++)
        #pragma unroll
        for (int j = 0; j < 4; j++)
            #pragma unroll
            for (int q = 0; q < 4; q++) acc[i][j][q] = 0.f;

    auto issue = [&](int chunk, int buf) {
        uint32_t sb = sbase + buf * STAGE_BYTES;
        int kpos = chunk * BKK;
        #pragma unroll
        for (int i = 0; i < 4; i++) {
            int c = t + i * 256;
            int row = c >> 3, seg = c & 7;
            uint32_t so = (uint32_t)(row * SSTRIDE + seg * 8) * 2;
            size_t ga = (size_t)(m0 + row) * K + kpos + seg * 8;
            size_t gb = (size_t)(n0 + row) * K + kpos + seg * 8;
            cp16(sb + 0 * MAT_BYTES + so, Ahi + ga);
            cp16(sb + 1 * MAT_BYTES + so, Alo + ga);
            cp16(sb + 2 * MAT_BYTES + so, Bhi + gb);
            cp16(sb + 3 * MAT_BYTES + so, Blo + gb);
        }
        asm volatile("cp.async.commit_group;\n");
    };

    // per-thread fragment address offsets (bytes, within a matrix)
    const uint32_t aOff = (uint32_t)((wy * 64 + (lane & 15)) * SSTRIDE + ((lane >> 4) * 8)) * 2;
    const uint32_t bOff = (uint32_t)((wx * 32 + ((lane >> 4) * 8) + (lane & 7)) * SSTRIDE
                                     + (((lane >> 3) & 1) * 8)) * 2;

    // double-buffered fragments (pipelined across kk)
    uint32_t fah[2][4][4], fal[2][4][4], fbh[2][4][2], fbl[2][4][2];

    auto ldfrag = [&](uint32_t sb, int kk, int buf) {
        uint32_t kby = (uint32_t)(kk * 16) * 2;
        #pragma unroll
        for (int mt = 0; mt < 4; mt++) {
            uint32_t ad = sb + aOff + kby + (uint32_t)(mt * 16 * SSTRIDE) * 2;
            ldsm_x4(fah[buf][mt][0], fah[buf][mt][1], fah[buf][mt][2], fah[buf][mt][3], ad);
            ldsm_x4(fal[buf][mt][0], fal[buf][mt][1], fal[buf][mt][2], fal[buf][mt][3],
                    ad + MAT_BYTES);
        }
        #pragma unroll
        for (int p = 0; p < 2; p++) {
            uint32_t bd = sb + 2 * MAT_BYTES + bOff + kby + (uint32_t)(p * 16 * SSTRIDE) * 2;
            uint32_t r0, r1, r2, r3;
            ldsm_x4(r0, r1, r2, r3, bd);
            fbh[buf][p * 2][0] = r0; fbh[buf][p * 2][1] = r1;
            fbh[buf][p * 2 + 1][0] = r2; fbh[buf][p * 2 + 1][1] = r3;
            ldsm_x4(r0, r1, r2, r3, bd + MAT_BYTES);
            fbl[buf][p * 2][0] = r0; fbl[buf][p * 2][1] = r1;
            fbl[buf][p * 2 + 1][0] = r2; fbl[buf][p * 2 + 1][1] = r3;
        }
    };

    const int NK = K / BKK;
    int issued = 0;
    #pragma unroll
    for (int p = 0; p < NSTAGE; p++) {
        if (issued < NK) { issue(issued, issued % NSTAGE); issued++; }
    }

    for (int kt = 0; kt < NK; kt++) {
        int rem = issued - kt - 1;   // groups allowed to stay pending
        if (rem >= 2)      asm volatile("cp.async.wait_group 2;\n" ::: "memory");
        else if (rem == 1) asm volatile("cp.async.wait_group 1;\n" ::: "memory");
        else               asm volatile("cp.async.wait_group 0;\n" ::: "memory");
        __syncthreads();
        uint32_t sb = sbase + (kt % NSTAGE) * STAGE_BYTES;
        ldfrag(sb, 0, 0);
        #pragma unroll
        for (int kk = 0; kk < BKK / 16; kk++) {
            int cur = kk & 1;
            if (kk < BKK / 16 - 1) ldfrag(sb, kk + 1, cur ^ 1);
            #pragma unroll
            for (int mt = 0; mt < 4; mt++)
                #pragma unroll
                for (int nt = 0; nt < 4; nt++) {
                    mma16816(acc[mt][nt], fah[cur][mt], fbh[cur][nt]);
                    mma16816(acc[mt][nt], fah[cur][mt], fbl[cur][nt]);
                    mma16816(acc[mt][nt], fal[cur][mt], fbh[cur][nt]);
                }
        }
        __syncthreads();
        if (issued < NK) { issue(issued, issued % NSTAGE); issued++; }
    }

    // epilogue
    #pragma unroll
    for (int mt = 0; mt < 4; mt++) {
        int r = m0 + wy * 64 + mt * 16 + (lane >> 2);
        #pragma unroll
        for (int nt = 0; nt < 4; nt++) {
            int c = n0 + wx * 32 + nt * 8 + (lane & 3) * 2;
            float v00 = acc[mt][nt][0], v01 = acc[mt][nt][1];
            float v10 = acc[mt][nt][2], v11 = acc[mt][nt][3];
            if (MODE == 0) {
                float b0 = p0[c], b1 = p0[c + 1];
                v00 += b0; v01 += b1; v10 += b0; v11 += b1;
                __nv_bfloat16 h00 = __float2bfloat16(v00), h01 = __float2bfloat16(v01);
                __nv_bfloat16 h10 = __float2bfloat16(v10), h11 = __float2bfloat16(v11);
                __nv_bfloat162 hh;
                hh.x = h00; hh.y = h01; *(__nv_bfloat162*)&Chi[(size_t)r * N + c] = hh;
                hh.x = h10; hh.y = h11; *(__nv_bfloat162*)&Chi[(size_t)(r + 8) * N + c] = hh;
                __nv_bfloat162 ll;
                ll.x = __float2bfloat16(v00 - __bfloat162float(h00));
                ll.y = __float2bfloat16(v01 - __bfloat162float(h01));
                *(__nv_bfloat162*)&Clo[(size_t)r * N + c] = ll;
                ll.x = __float2bfloat16(v10 - __bfloat162float(h10));
                ll.y = __float2bfloat16(v11 - __bfloat162float(h11));
                *(__nv_bfloat162*)&Clo[(size_t)(r + 8) * N + c] = ll;
            } else {
                float s0 = rsqrtf(p3[c] + BN_EPS) * p0[c];
                float s1 = rsqrtf(p3[c + 1] + BN_EPS) * p0[c + 1];
                float t0 = p1[c] - p2[c] * s0;
                float t1 = p1[c + 1] - p2[c + 1] * s1;
                float2 o0 = {v00 * s0 + t0, v01 * s1 + t1};
                float2 o1 = {v10 * s0 + t0, v11 * s1 + t1};
                *(float2*)&C[(size_t)r * N + c] = o0;
                *(float2*)&C[(size_t)(r + 8) * N + c] = o1;
            }
        }
    }
}

// ---------------- K3: attention = sigmoid(h @ fc2_w^T + b), h = hi + lo (vectorized) -----
__global__ void att_kernel(const __nv_bfloat16* __restrict__ hhi,
                           const __nv_bfloat16* __restrict__ hlo,
                           const float* __restrict__ w2,
                           const float* __restrict__ b2, float* __restrict__ att) {
    int m = blockIdx.x;
    int warp = threadIdx.x >> 5, lane = threadIdx.x & 31;
    const __nv_bfloat16* hr = hhi + (size_t)m * ED_;
    const __nv_bfloat16* lr = hlo + (size_t)m * ED_;
    const float* wr = w2 + (size_t)warp * ED_;
    float s = 0.f;
    for (int k = lane * 2; k < ED_; k += 64) {
        __nv_bfloat162 a = *(const __nv_bfloat162*)&hr[k];
        __nv_bfloat162 b = *(const __nv_bfloat162*)&lr[k];
        float2 w = *(const float2*)&wr[k];
        s += (__bfloat162float(a.x) + __bfloat162float(b.x)) * w.x
           + (__bfloat162float(a.y) + __bfloat162float(b.y)) * w.y;
    }
    for (int o = 16; o; o >>= 1) s += __shfl_xor_sync(0xffffffffu, s, o);
    if (lane == 0) {
        float v = s + b2[warp];
        att[m * G_ + warp] = 1.f / (1.f + expf(-v));
    }
}

// ---------------- K6: softmax over K within each group, times attention ----------------
__global__ void softmax_att_kernel(const float* __restrict__ act, const float* __restrict__ att,
                                   float* __restrict__ actn) {
    int m = blockIdx.x;
    int g = threadIdx.x >> 5, lane = threadIdx.x & 31;
    const float* row = act + (size_t)m * (G_ * K_) + g * K_;
    float v0 = row[lane], v1 = row[lane + 32];
    float mx = fmaxf(v0, v1);
    for (int o = 16; o; o >>= 1) mx = fmaxf(mx, __shfl_xor_sync(0xffffffffu, mx, o));
    float e0 = expf(v0 - mx), e1 = expf(v1 - mx);
    float s = e0 + e1;
    for (int o = 16; o; o >>= 1) s += __shfl_xor_sync(0xffffffffu, s, o);
    float scl = att[m * G_ + g] / s;
    float* orow = actn + (size_t)m * (G_ * K_) + g * K_;
    orow[lane] = e0 * scl;
    orow[lane + 32] = e1 * scl;
}

// ---------------- K7: asum[b,k] ----------------
__global__ void asum_kernel(const float* __restrict__ actn, float* __restrict__ asum) {
    int b = blockIdx.x;
    int t = threadIdx.x;
    int k = t & 63, grp = t >> 6;
    float s = 0.f;
    for (int n = grp; n < N2_; n += 4) {
        int row = b * FR_ + (n >> 3);
        s += actn[(size_t)row * (G_ * K_) + (n & 7) * K_ + k];
    }
    __shared__ float red[256];
    red[t] = s;
    __syncthreads();
    if (grp == 0) {
        float tot = red[k] + red[64 + k] + red[128 + k] + red[192 + k];
        asum[b * K_ + k] = tot;
    }
}

// ---------------- K8: batched VLAD GEMM, h = hi + lo (vectorized loads) ----------------
__global__ void vlad_gemm_kernel(const __nv_bfloat16* __restrict__ hhi,
                                 const __nv_bfloat16* __restrict__ hlo,
                                 const float* __restrict__ actn,
                                 const float* __restrict__ asum, const float* __restrict__ c2,
                                 float* __restrict__ vlad) {
    int b  = blockIdx.x;
    int f0 = blockIdx.y * 64;
    __shared__ float Rs[32][68];
    __shared__ float Qs[32][68];
    int t = threadIdx.x;
    int tx = t & 15, ty = t >> 4;
    float acc[4][4];
    #pragma unroll
    for (int i = 0; i < 4; i++)
        #pragma unroll
        for (int j = 0; j < 4; j++) acc[i][j] = 0.f;

    for (int n0 = 0; n0 < N2_; n0 += 32) {
        __syncthreads();
        #pragma unroll
        for (int i = 0; i < 4; i++) {           // Rs: 1024 bf162 pairs
            int idx = t + i * 256;
            int n = idx >> 5, fp = idx & 31;
            int f = fp * 2;
            int nn = n0 + n;
            int row = b * FR_ + (nn >> 3);
            size_t hidx = (size_t)row * ED_ + (nn & 7) * FEAT_ + f0 + f;
            __nv_bfloat162 hv = *(const __nv_bfloat162*)&hhi[hidx];
            __nv_bfloat162 lv = *(const __nv_bfloat162*)&hlo[hidx];
            Rs[n][f]     = __bfloat162float(hv.x) + __bfloat162float(lv.x);
            Rs[n][f + 1] = __bfloat162float(hv.y) + __bfloat162float(lv.y);
        }
        #pragma unroll
        for (int i = 0; i < 8; i++) {           // Qs: fp32
            int idx = t + i * 256;
            int n = idx >> 6, f = idx & 63;
            int nn = n0 + n;
            int row = b * FR_ + (nn >> 3);
            Qs[n][f] = actn[(size_t)row * (G_ * K_) + (nn & 7) * K_ + f];
        }
        __syncthreads();
        #pragma unroll
        for (int nn = 0; nn < 32; nn++) {
            float rf[4], qf[4];
            *(float4*)rf = *(const float4*)&Rs[nn][ty * 4];
            *(float4*)qf = *(const float4*)&Qs[nn][tx * 4];
            #pragma unroll
            for (int i = 0; i < 4; i++)
                #pragma unroll
                for (int j = 0; j < 4; j++) acc[i][j] += rf[i] * qf[j];
        }
    }
    #pragma unroll
    for (int i = 0; i < 4; i++) {
        int f = f0 + ty * 4 + i;
        #pragma unroll
        for (int j = 0; j < 4; j++) {
            int k = tx * 4 + j;
            float v = acc[i][j] - asum[b * K_ + k] * c2[(size_t)f * K_ + k];
            vlad[((size_t)b * FEAT_ + f) * K_ + k] = v;
        }
    }
}

// ---------------- K9: intra-norm + BN2 ----------------
__global__ void intranorm_bn_kernel(const float* __restrict__ vlad, float* __restrict__ vladn,
                                    const float* __restrict__ g, const float* __restrict__ bb,
                                    const float* __restrict__ mm, const float* __restrict__ vv) {
    int b = blockIdx.x;
    int t = threadIdx.x;
    int k = t & 63, fg = t >> 6;
    float s = 0.f;
    for (int f = fg; f < FEAT_; f += 8) {
        float x = vlad[((size_t)b * FEAT_ + f) * K_ + k];
        s += x * x;
    }
    __shared__ float red[512];
    red[t] = s;
    __syncthreads();
    if (fg == 0) {
        float tot = 0.f;
        #pragma unroll
        for (int i = 0; i < 8; i++) tot += red[i * 64 + k];
        red[k] = 1.f / fmaxf(sqrtf(tot), L2_EPS);
    }
    __syncthreads();
    float inv = red[k];
    for (int f = fg; f < FEAT_; f += 8) {
        int idx = f * K_ + k;
        float x = vlad[((size_t)b * FEAT_ + f) * K_ + k] * inv;
        vladn[(size_t)b * VLAD_ + idx] =
            (x - mm[idx]) * rsqrtf(vv[idx] + BN_EPS) * g[idx] + bb[idx];
    }
}

// ---------------- K10: broadcast bias init ----------------
__global__ void bias_init_kernel(float* __restrict__ C, const float* __restrict__ bias,
                                 int rows, int N) {
    int idx = blockIdx.x * blockDim.x + threadIdx.x;
    if (idx < rows * N) C[idx] = bias[idx % N];
}

// ---------------- K11: skinny GEMM (split-K, atomic) ----------------
__global__ void skinny32_kernel(const float* __restrict__ A, const float* __restrict__ W,
                                float* __restrict__ C, int N, int K, int KC) {
    int o0 = blockIdx.x * 128;
    int k0 = blockIdx.y * KC;
    __shared__ float As[32][36];
    __shared__ float Ws[32][132];
    int t = threadIdx.x;
    int kl = t & 31, rg = t >> 5;
    int oq = t & 31, bq = t >> 5;
    float acc[4][4];
    #pragma unroll
    for (int i = 0; i < 4; i++)
        #pragma unroll
        for (int j = 0; j < 4; j++) acc[i][j] = 0.f;

    int kend = min(k0 + KC, K);
    for (int kt = k0; kt < kend; kt += 32) {
        __syncthreads();
        #pragma unroll
        for (int i = 0; i < 4; i++) {
            int b = rg + i * 8;
            As[kl][b] = A[(size_t)b * K + kt + kl];
        }
        #pragma unroll
        for (int i = 0; i < 16; i++) {
            int o = rg + i * 8;
            int og = o0 + o;
            Ws[kl][o] = (og < N) ? W[(size_t)og * K + kt + kl] : 0.f;
        }
        __syncthreads();
        #pragma unroll
        for (int kk = 0; kk < 32; kk++) {
            float4 w4 = *(const float4*)&Ws[kk][oq * 4];
            float4 a4 = *(const float4*)&As[kk][bq * 4];
            float av[4] = {a4.x, a4.y, a4.z, a4.w};
            float wv[4] = {w4.x, w4.y, w4.z, w4.w};
            #pragma unroll
            for (int i = 0; i < 4; i++)
                #pragma unroll
                for (int j = 0; j < 4; j++) acc[i][j] += av[i] * wv[j];
        }
    }
    #pragma unroll
    for (int i = 0; i < 4; i++) {
        int b = bq * 4 + i;
        #pragma unroll
        for (int j = 0; j < 4; j++) {
            int o = o0 + oq * 4 + j;
            if (o < N) atomicAdd(&C[(size_t)b * N + o], acc[i][j]);
        }
    }
}

// ---------------- K12: BN ----------------
__global__ void bn_kernel(const float* __restrict__ in, float* __restrict__ out,
                          const float* __restrict__ g, const float* __restrict__ bb,
                          const float* __restrict__ mm, const float* __restrict__ vv,
                          int rows, int N) {
    int idx = blockIdx.x * blockDim.x + threadIdx.x;
    if (idx < rows * N) {
        int c = idx % N;
        out[idx] = (in[idx] - mm[c]) * rsqrtf(vv[c] + BN_EPS) * g[c] + bb[c];
    }
}

// ---------------- K13/K14: SE gating ----------------
__global__ void se1_kernel(const float* __restrict__ y, const float* __restrict__ w,
                           const float* __restrict__ bias,
                           const float* __restrict__ g, const float* __restrict__ bb,
                           const float* __restrict__ mm, const float* __restrict__ vv,
                           float* __restrict__ z) {
    int warp = threadIdx.x >> 5, lane = threadIdx.x & 31;
    int idx = blockIdx.x * 8 + warp;
    int b = idx / HR_, o = idx % HR_;
    const float* yr = y + (size_t)b * H_;
    const float* wr = w + (size_t)o * H_;
    float s = 0.f;
    for (int k = lane; k < H_; k += 32) s += yr[k] * wr[k];
    for (int off = 16; off; off >>= 1) s += __shfl_xor_sync(0xffffffffu, s, off);
    if (lane == 0) {
        float v = s + bias[o];
        v = (v - mm[o]) * rsqrtf(vv[o] + BN_EPS) * g[o] + bb[o];
        z[(size_t)b * HR_ + o] = fmaxf(v, 0.f);
    }
}

__global__ void se2_kernel(const float* __restrict__ z, const float* __restrict__ w,
                           const float* __restrict__ bias, const float* __restrict__ y,
                           float* __restrict__ yg) {
    int warp = threadIdx.x >> 5, lane = threadIdx.x & 31;
    int idx = blockIdx.x * 8 + warp;
    int b = idx / H_, o = idx % H_;
    const float* zr = z + (size_t)b * HR_;
    const float* wr = w + (size_t)o * HR_;
    float s = 0.f;
    for (int k = lane; k < HR_; k += 32) s += zr[k] * wr[k];
    for (int off = 16; off; off >>= 1) s += __shfl_xor_sync(0xffffffffu, s, off);
    if (lane == 0) {
        float gate = 1.f / (1.f + expf(-(s + bias[o])));
        yg[(size_t)b * H_ + o] = y[(size_t)b * H_ + o] * gate;
    }
}

// ---------------- host launcher ----------------
extern "C" void kernel_launch(void* const* d_in, const int* in_sizes, int n_in,
                              void* d_out, int out_size) {
    const float* x     = (const float*)d_in[0];
    const float* fc1_w = (const float*)d_in[1];
    const float* fc1_b = (const float*)d_in[2];
    const float* fc2_w = (const float*)d_in[3];
    const float* fc2_b = (const float*)d_in[4];
    const float* c1    = (const float*)d_in[5];
    const float* c2    = (const float*)d_in[6];
    const float* bn1_g = (const float*)d_in[7];
    const float* bn1_b = (const float*)d_in[8];
    const float* bn1_m = (const float*)d_in[9];
    const float* bn1_v = (const float*)d_in[10];
    const float* bn2_g = (const float*)d_in[11];
    const float* bn2_b = (const float*)d_in[12];
    const float* bn2_m = (const float*)d_in[13];
    const float* bn2_v = (const float*)d_in[14];
    const float* cgf_w = (const float*)d_in[15];
    const float* cgf_b = (const float*)d_in[16];
    const float* cgbn_g = (const float*)d_in[17];
    const float* cgbn_b = (const float*)d_in[18];
    const float* cgbn_m = (const float*)d_in[19];
    const float* cgbn_v = (const float*)d_in[20];
    const float* g1_w  = (const float*)d_in[21];
    const float* g1_b  = (const float*)d_in[22];
    const float* gbn_g = (const float*)d_in[23];
    const float* gbn_b = (const float*)d_in[24];
    const float* gbn_m = (const float*)d_in[25];
    const float* gbn_v = (const float*)d_in[26];
    const float* g2_w  = (const float*)d_in[27];
    const float* g2_b  = (const float*)d_in[28];
    const float* fc3_w = (const float*)d_in[29];
    const float* fc3_b = (const float*)d_in[30];
    float* out = (float*)d_out;

    float *rinv, *att, *act, *actn, *asum, *vlad, *vladn, *y0, *y, *z, *yg;
    __nv_bfloat16 *xhi, *xlo, *whi, *wlo, *hhi, *hlo, *c1hi, *c1lo;
    cudaGetSymbolAddress((void**)&rinv,  g_rinv);
    cudaGetSymbolAddress((void**)&att,   g_att);
    cudaGetSymbolAddress((void**)&act,   g_act);
    cudaGetSymbolAddress((void**)&actn,  g_actn);
    cudaGetSymbolAddress((void**)&asum,  g_asum);
    cudaGetSymbolAddress((void**)&vlad,  g_vlad);
    cudaGetSymbolAddress((void**)&vladn, g_vladn);
    cudaGetSymbolAddress((void**)&y0,    g_y0);
    cudaGetSymbolAddress((void**)&y,     g_y);
    cudaGetSymbolAddress((void**)&z,     g_z);
    cudaGetSymbolAddress((void**)&yg,    g_yg);
    cudaGetSymbolAddress((void**)&xhi,   g_xhi);
    cudaGetSymbolAddress((void**)&xlo,   g_xlo);
    cudaGetSymbolAddress((void**)&whi,   g_whi);
    cudaGetSymbolAddress((void**)&wlo,   g_wlo);
    cudaGetSymbolAddress((void**)&hhi,   g_hhi);
    cudaGetSymbolAddress((void**)&hlo,   g_hlo);
    cudaGetSymbolAddress((void**)&c1hi,  g_c1hi);
    cudaGetSymbolAddress((void**)&c1lo,  g_c1lo);

    cudaFuncSetAttribute(mma_gemm_kernel<0>, cudaFuncAttributeMaxDynamicSharedMemorySize, GEMM_SMEM);
    cudaFuncSetAttribute(mma_gemm_kernel<1>, cudaFuncAttributeMaxDynamicSharedMemorySize, GEMM_SMEM);

    // 1. row inverse norms of x
    rownorm_inv_kernel<<<M_, 256>>>(x, rinv);

    // 2. split x (scaled by rinv) and fc1_w into bf16 hi/lo
    split_kernel<<<(M_ * D_ / 4 + 255) / 256, 256>>>(x, xhi, xlo, M_ * D_, rinv, D_);
    split_kernel<<<(ED_ * D_ / 4 + 255) / 256, 256>>>(fc1_w, whi, wlo, ED_ * D_, nullptr, 0);

    // 3. h (bf16 hi/lo only) = xn @ fc1_w^T + fc1_b — tensor cores
    mma_gemm_kernel<0><<<dim3(ED_ / BN, M_ / BM), 256, GEMM_SMEM>>>(
        xhi, xlo, whi, wlo, nullptr, hhi, hlo, M_, ED_, D_, fc1_b, nullptr, nullptr, nullptr);

    // 4. attention
    att_kernel<<<M_, 256>>>(hhi, hlo, fc2_w, fc2_b, att);

    // 5. c1^T + split, fused
    transpose_split_kernel<<<dim3((G_ * K_) / 32, ED_ / 32), 256>>>(c1, c1hi, c1lo, ED_, G_ * K_);

    // 6. act = BN1(h @ c1) — tensor cores
    mma_gemm_kernel<1><<<dim3((G_ * K_) / BN, M_ / BM), 256, GEMM_SMEM>>>(
        hhi, hlo, c1hi, c1lo, act, nullptr, nullptr, M_, G_ * K_, ED_,
        bn1_g, bn1_b, bn1_m, bn1_v);

    // 7. softmax * att
    softmax_att_kernel<<<M_, 256>>>(act, att, actn);

    // 8. asum
    asum_kernel<<<B_, 256>>>(actn, asum);

    // 9. vlad
    vlad_gemm_kernel<<<dim3(B_, FEAT_ / 64), 256>>>(hhi, hlo, actn, asum, c2, vlad);

    // 10. intra-norm + BN2
    intranorm_bn_kernel<<<B_, 512>>>(vlad, vladn, bn2_g, bn2_b, bn2_m, bn2_v);

    // 11. y = BN(vladn @ cgf_w^T + cgf_b)
    bias_init_kernel<<<(B_ * H_ + 255) / 256, 256>>>(y0, cgf_b, B_, H_);
    skinny32_kernel<<<dim3(H_ / 128, 16), 256>>>(vladn, cgf_w, y0, H_, VLAD_, VLAD_ / 16);
    bn_kernel<<<(B_ * H_ + 255) / 256, 256>>>(y0, y, cgbn_g, cgbn_b, cgbn_m, cgbn_v, B_, H_);

    // 12. SE gating
    se1_kernel<<<(B_ * HR_) / 8, 256>>>(y, g1_w, g1_b, gbn_g, gbn_b, gbn_m, gbn_v, z);
    se2_kernel<<<(B_ * H_) / 8, 256>>>(z, g2_w, g2_b, y, yg);

    // 13. out = yg @ fc3_w^T + fc3_b
    bias_init_kernel<<<(B_ * NC_ + 255) / 256, 256>>>(out, fc3_b, B_, NC_);
    skinny32_kernel<<<dim3((NC_ + 127) / 128, 8), 256>>>(yg, fc3_w, out, NC_, H_, H_ / 8);
}

// round 7
// speedup vs baseline: 1.0472x; 1.0135x over previous
#include <cuda_runtime.h>
#include <cuda_bf16.h>
#include <math.h>
#include <stdint.h>

// ---------------- problem constants ----------------
#define B_    32
#define FR_   300
#define D_    2048
#define ED_   4096      // E*D
#define G_    8
#define K_    64
#define FEAT_ 512       // E*D/G
#define VLAD_ 32768     // K*FEAT
#define H_    2048
#define HR_   256       // H/R
#define NC_   3862
#define M_    (B_*FR_)  // 9600
#define N2_   2400      // FR*G
#define BN_EPS 1e-5f
#define L2_EPS 1e-12f

// ---------------- scratch (device globals; no allocs allowed) ----------------
__device__ __align__(128) float g_rinv[M_];
__device__ __align__(128) float g_att[M_ * G_];
__device__ __align__(128) float g_act[M_ * (G_*K_)];
__device__ __align__(128) float g_actn[M_ * (G_*K_)];
__device__ __align__(128) float g_asum[B_ * K_];
__device__ __align__(128) float g_vlad[B_ * FEAT_ * K_];
__device__ __align__(128) float g_vladn[B_ * VLAD_];
__device__ __align__(128) float g_y0[B_ * H_];
__device__ __align__(128) float g_y[B_ * H_];
__device__ __align__(128) float g_z[B_ * HR_];
__device__ __align__(128) float g_yg[B_ * H_];
// bf16 hi/lo split buffers
__device__ __align__(128) __nv_bfloat16 g_xhi[M_ * D_];
__device__ __align__(128) __nv_bfloat16 g_xlo[M_ * D_];
__device__ __align__(128) __nv_bfloat16 g_whi[ED_ * D_];
__device__ __align__(128) __nv_bfloat16 g_wlo[ED_ * D_];
__device__ __align__(128) __nv_bfloat16 g_hhi[M_ * ED_];
__device__ __align__(128) __nv_bfloat16 g_hlo[M_ * ED_];
__device__ __align__(128) __nv_bfloat16 g_c1hi[(G_*K_) * ED_];
__device__ __align__(128) __nv_bfloat16 g_c1lo[(G_*K_) * ED_];

// ---------------- K1: per-row inverse L2 norm of x ----------------
__global__ void rownorm_inv_kernel(const float* __restrict__ x, float* __restrict__ rinv) {
    int m = blockIdx.x;
    int t = threadIdx.x;
    float s = 0.f;
    const float* row = x + (size_t)m * D_;
    for (int k = t; k < D_; k += 256) { float v = row[k]; s += v * v; }
    for (int o = 16; o; o >>= 1) s += __shfl_xor_sync(0xffffffffu, s, o);
    __shared__ float red[8];
    if ((t & 31) == 0) red[t >> 5] = s;
    __syncthreads();
    if (t == 0) {
        float tot = 0.f;
        #pragma unroll
        for (int i = 0; i < 8; i++) tot += red[i];
        rinv[m] = 1.f / fmaxf(sqrtf(tot), L2_EPS);
    }
}

// ---------------- K2: fp32 -> bf16 hi/lo split (optional per-row scale) ----------------
__global__ void split_kernel(const float* __restrict__ src,
                             __nv_bfloat16* __restrict__ hi, __nv_bfloat16* __restrict__ lo,
                             int n, const float* __restrict__ rowscale, int rowlen) {
    int i = (blockIdx.x * blockDim.x + threadIdx.x) * 4;
    if (i >= n) return;
    float4 v = *(const float4*)(src + i);
    if (rowscale) {
        float s = rowscale[i / rowlen];
        v.x *= s; v.y *= s; v.z *= s; v.w *= s;
    }
    __nv_bfloat16 h0 = __float2bfloat16(v.x), h1 = __float2bfloat16(v.y);
    __nv_bfloat16 h2 = __float2bfloat16(v.z), h3 = __float2bfloat16(v.w);
    __nv_bfloat162 a; a.x = h0; a.y = h1;
    __nv_bfloat162 b; b.x = h2; b.y = h3;
    *(__nv_bfloat162*)&hi[i]     = a;
    *(__nv_bfloat162*)&hi[i + 2] = b;
    a.x = __float2bfloat16(v.x - __bfloat162float(h0));
    a.y = __float2bfloat16(v.y - __bfloat162float(h1));
    b.x = __float2bfloat16(v.z - __bfloat162float(h2));
    b.y = __float2bfloat16(v.w - __bfloat162float(h3));
    *(__nv_bfloat162*)&lo[i]     = a;
    *(__nv_bfloat162*)&lo[i + 2] = b;
}

// ---------------- K2b: fused transpose + split: c1[R,C] -> c1hi/lo[C,R] ----------------
__global__ void transpose_split_kernel(const float* __restrict__ in,
                                       __nv_bfloat16* __restrict__ hi,
                                       __nv_bfloat16* __restrict__ lo, int R, int C) {
    __shared__ float tile[32][33];
    int c0 = blockIdx.x * 32, r0 = blockIdx.y * 32;
    int tx = threadIdx.x & 31, ty = threadIdx.x >> 5;   // 256 thr
    #pragma unroll
    for (int i = 0; i < 32; i += 8)
        tile[ty + i][tx] = in[(size_t)(r0 + ty + i) * C + c0 + tx];
    __syncthreads();
    #pragma unroll
    for (int i = 0; i < 32; i += 8) {
        float v = tile[tx][ty + i];
        __nv_bfloat16 hv = __float2bfloat16(v);
        size_t idx = (size_t)(c0 + ty + i) * R + r0 + tx;
        hi[idx] = hv;
        lo[idx] = __float2bfloat16(v - __bfloat162float(hv));
    }
}

// ---------------- tensor-core GEMM: C[M,N] = A[M,K] * B[N,K]^T  (bf16 split, fp32 acc) ----
// BK=32, 2 stages, 80KB smem -> 2 CTAs/SM to hide sync/epilogue bubbles.
#define BM 128
#define BN 128
#define BKK 32
#define SSTRIDE 40                        // BKK + 8 (conflict-mitigated ldmatrix)
#define MAT_BYTES (128 * SSTRIDE * 2)     // 10240
#define STAGE_BYTES (4 * MAT_BYTES)       // 40960
#define GEMM_SMEM (2 * STAGE_BYTES)       // 81920  (2 CTAs/SM: 163840 <= 227KB)

__device__ __forceinline__ void cp16(uint32_t dst, const void* src) {
    asm volatile("cp.async.cg.shared.global [%0], [%1], 16;\n" :: "r"(dst), "l"(src));
}
__device__ __forceinline__ void ldsm_x4(uint32_t& r0, uint32_t& r1, uint32_t& r2, uint32_t& r3,
                                        uint32_t addr) {
    asm volatile("ldmatrix.sync.aligned.m8n8.x4.shared.b16 {%0,%1,%2,%3}, [%4];\n"
                 : "=r"(r0), "=r"(r1), "=r"(r2), "=r"(r3) : "r"(addr));
}
__device__ __forceinline__ void mma16816(float* c, const uint32_t* a, const uint32_t* b) {
    asm volatile("mma.sync.aligned.m16n8k16.row.col.f32.bf16.bf16.f32 "
                 "{%0,%1,%2,%3},{%4,%5,%6,%7},{%8,%9},{%0,%1,%2,%3};\n"
                 : "+f"(c[0]), "+f"(c[1]), "+f"(c[2]), "+f"(c[3])
                 : "r"(a[0]), "r"(a[1]), "r"(a[2]), "r"(a[3]), "r"(b[0]), "r"(b[1]));
}

// MODE 0: emit Chi/Clo = bf16 split of (acc + p0[n])   (no fp32 C)
// MODE 1: emit C fp32 = (acc - p2[n])*rsqrt(p3[n]+eps)*p0[n] + p1[n]
template <int MODE>
__global__ __launch_bounds__(256, 2)
void mma_gemm_kernel(const __nv_bfloat16* __restrict__ Ahi, const __nv_bfloat16* __restrict__ Alo,
                     const __nv_bfloat16* __restrict__ Bhi, const __nv_bfloat16* __restrict__ Blo,
                     float* __restrict__ C, __nv_bfloat16* __restrict__ Chi,
                     __nv_bfloat16* __restrict__ Clo, int M, int N, int K,
                     const float* __restrict__ p0, const float* __restrict__ p1,
                     const float* __restrict__ p2, const float* __restrict__ p3) {
    extern __shared__ __align__(16) unsigned char smem_raw[];
    uint32_t sbase = (uint32_t)__cvta_generic_to_shared(smem_raw);

    const int t = threadIdx.x;
    const int lane = t & 31;
    const int warp = t >> 5;
    const int wy = warp >> 2;       // 0..1 (M)
    const int wx = warp & 3;        // 0..3 (N)
    const int m0 = blockIdx.y * BM;
    const int n0 = blockIdx.x * BN;

    float acc[4][4][4];
    #pragma unroll
    for (int i = 0; i < 4; i++)
        #pragma unroll
        for (int j = 0; j < 4; j++)
            #pragma unroll
            for (int q = 0; q < 4; q++) acc[i][j][q] = 0.f;

    // loader: 512 16B-chunks per 128x32 matrix, 4 matrices -> 8 cp16/thread
    auto issue = [&](int chunk, int buf) {
        uint32_t sb = sbase + buf * STAGE_BYTES;
        int kpos = chunk * BKK;
        #pragma unroll
        for (int i = 0; i < 2; i++) {
            int c = t + i * 256;               // 0..511
            int row = c >> 2, seg = c & 3;     // 4 segs of 8 bf16 per row
            uint32_t so = (uint32_t)(row * SSTRIDE + seg * 8) * 2;
            size_t ga = (size_t)(m0 + row) * K + kpos + seg * 8;
            size_t gb = (size_t)(n0 + row) * K + kpos + seg * 8;
            cp16(sb + 0 * MAT_BYTES + so, Ahi + ga);
            cp16(sb + 1 * MAT_BYTES + so, Alo + ga);
            cp16(sb + 2 * MAT_BYTES + so, Bhi + gb);
            cp16(sb + 3 * MAT_BYTES + so, Blo + gb);
        }
        asm volatile("cp.async.commit_group;\n");
    };

    // per-thread fragment address offsets (bytes, within a matrix)
    const uint32_t aOff = (uint32_t)((wy * 64 + (lane & 15)) * SSTRIDE + ((lane >> 4) * 8)) * 2;
    const uint32_t bOff = (uint32_t)((wx * 32 + ((lane >> 4) * 8) + (lane & 7)) * SSTRIDE
                                     + (((lane >> 3) & 1) * 8)) * 2;

    const int NK = K / BKK;
    issue(0, 0);

    for (int kt = 0; kt < NK; kt++) {
        if (kt + 1 < NK) {
            issue(kt + 1, (kt + 1) & 1);
            asm volatile("cp.async.wait_group 1;\n" ::: "memory");
        } else {
            asm volatile("cp.async.wait_group 0;\n" ::: "memory");
        }
        __syncthreads();
        uint32_t sb = sbase + (kt & 1) * STAGE_BYTES;
        #pragma unroll
        for (int kk = 0; kk < BKK / 16; kk++) {
            uint32_t kby = (uint32_t)(kk * 16) * 2;
            uint32_t ahi[4][4], alo[4][4], bhi[4][2], blo[4][2];
            #pragma unroll
            for (int mt = 0; mt < 4; mt++) {
                uint32_t ad = sb + aOff + kby + (uint32_t)(mt * 16 * SSTRIDE) * 2;
                ldsm_x4(ahi[mt][0], ahi[mt][1], ahi[mt][2], ahi[mt][3], ad);
                ldsm_x4(alo[mt][0], alo[mt][1], alo[mt][2], alo[mt][3], ad + MAT_BYTES);
            }
            #pragma unroll
            for (int p = 0; p < 2; p++) {
                uint32_t bd = sb + 2 * MAT_BYTES + bOff + kby + (uint32_t)(p * 16 * SSTRIDE) * 2;
                uint32_t r0, r1, r2, r3;
                ldsm_x4(r0, r1, r2, r3, bd);
                bhi[p * 2][0] = r0; bhi[p * 2][1] = r1;
                bhi[p * 2 + 1][0] = r2; bhi[p * 2 + 1][1] = r3;
                ldsm_x4(r0, r1, r2, r3, bd + MAT_BYTES);
                blo[p * 2][0] = r0; blo[p * 2][1] = r1;
                blo[p * 2 + 1][0] = r2; blo[p * 2 + 1][1] = r3;
            }
            #pragma unroll
            for (int mt = 0; mt < 4; mt++)
                #pragma unroll
                for (int nt = 0; nt < 4; nt++) {
                    mma16816(acc[mt][nt], ahi[mt], bhi[nt]);
                    mma16816(acc[mt][nt], ahi[mt], blo[nt]);
                    mma16816(acc[mt][nt], alo[mt], bhi[nt]);
                }
        }
        __syncthreads();
    }

    // epilogue
    #pragma unroll
    for (int mt = 0; mt < 4; mt++) {
        int r = m0 + wy * 64 + mt * 16 + (lane >> 2);
        #pragma unroll
        for (int nt = 0; nt < 4; nt++) {
            int c = n0 + wx * 32 + nt * 8 + (lane & 3) * 2;
            float v00 = acc[mt][nt][0], v01 = acc[mt][nt][1];
            float v10 = acc[mt][nt][2], v11 = acc[mt][nt][3];
            if (MODE == 0) {
                float b0 = p0[c], b1 = p0[c + 1];
                v00 += b0; v01 += b1; v10 += b0; v11 += b1;
                __nv_bfloat16 h00 = __float2bfloat16(v00), h01 = __float2bfloat16(v01);
                __nv_bfloat16 h10 = __float2bfloat16(v10), h11 = __float2bfloat16(v11);
                __nv_bfloat162 hh;
                hh.x = h00; hh.y = h01; *(__nv_bfloat162*)&Chi[(size_t)r * N + c] = hh;
                hh.x = h10; hh.y = h11; *(__nv_bfloat162*)&Chi[(size_t)(r + 8) * N + c] = hh;
                __nv_bfloat162 ll;
                ll.x = __float2bfloat16(v00 - __bfloat162float(h00));
                ll.y = __float2bfloat16(v01 - __bfloat162float(h01));
                *(__nv_bfloat162*)&Clo[(size_t)r * N + c] = ll;
                ll.x = __float2bfloat16(v10 - __bfloat162float(h10));
                ll.y = __float2bfloat16(v11 - __bfloat162float(h11));
                *(__nv_bfloat162*)&Clo[(size_t)(r + 8) * N + c] = ll;
            } else {
                float s0 = rsqrtf(p3[c] + BN_EPS) * p0[c];
                float s1 = rsqrtf(p3[c + 1] + BN_EPS) * p0[c + 1];
                float t0 = p1[c] - p2[c] * s0;
                float t1 = p1[c + 1] - p2[c + 1] * s1;
                float2 o0 = {v00 * s0 + t0, v01 * s1 + t1};
                float2 o1 = {v10 * s0 + t0, v11 * s1 + t1};
                *(float2*)&C[(size_t)r * N + c] = o0;
                *(float2*)&C[(size_t)(r + 8) * N + c] = o1;
            }
        }
    }
}

// ---------------- K3: attention = sigmoid(h @ fc2_w^T + b), h = hi + lo (vectorized) -----
__global__ void att_kernel(const __nv_bfloat16* __restrict__ hhi,
                           const __nv_bfloat16* __restrict__ hlo,
                           const float* __restrict__ w2,
                           const float* __restrict__ b2, float* __restrict__ att) {
    int m = blockIdx.x;
    int warp = threadIdx.x >> 5, lane = threadIdx.x & 31;
    const __nv_bfloat16* hr = hhi + (size_t)m * ED_;
    const __nv_bfloat16* lr = hlo + (size_t)m * ED_;
    const float* wr = w2 + (size_t)warp * ED_;
    float s = 0.f;
    for (int k = lane * 2; k < ED_; k += 64) {
        __nv_bfloat162 a = *(const __nv_bfloat162*)&hr[k];
        __nv_bfloat162 b = *(const __nv_bfloat162*)&lr[k];
        float2 w = *(const float2*)&wr[k];
        s += (__bfloat162float(a.x) + __bfloat162float(b.x)) * w.x
           + (__bfloat162float(a.y) + __bfloat162float(b.y)) * w.y;
    }
    for (int o = 16; o; o >>= 1) s += __shfl_xor_sync(0xffffffffu, s, o);
    if (lane == 0) {
        float v = s + b2[warp];
        att[m * G_ + warp] = 1.f / (1.f + expf(-v));
    }
}

// ---------------- K6: softmax over K within each group, times attention ----------------
__global__ void softmax_att_kernel(const float* __restrict__ act, const float* __restrict__ att,
                                   float* __restrict__ actn) {
    int m = blockIdx.x;
    int g = threadIdx.x >> 5, lane = threadIdx.x & 31;
    const float* row = act + (size_t)m * (G_ * K_) + g * K_;
    float v0 = row[lane], v1 = row[lane + 32];
    float mx = fmaxf(v0, v1);
    for (int o = 16; o; o >>= 1) mx = fmaxf(mx, __shfl_xor_sync(0xffffffffu, mx, o));
    float e0 = expf(v0 - mx), e1 = expf(v1 - mx);
    float s = e0 + e1;
    for (int o = 16; o; o >>= 1) s += __shfl_xor_sync(0xffffffffu, s, o);
    float scl = att[m * G_ + g] / s;
    float* orow = actn + (size_t)m * (G_ * K_) + g * K_;
    orow[lane] = e0 * scl;
    orow[lane + 32] = e1 * scl;
}

// ---------------- K7: asum[b,k] ----------------
__global__ void asum_kernel(const float* __restrict__ actn, float* __restrict__ asum) {
    int b = blockIdx.x;
    int t = threadIdx.x;
    int k = t & 63, grp = t >> 6;
    float s = 0.f;
    for (int n = grp; n < N2_; n += 4) {
        int row = b * FR_ + (n >> 3);
        s += actn[(size_t)row * (G_ * K_) + (n & 7) * K_ + k];
    }
    __shared__ float red[256];
    red[t] = s;
    __syncthreads();
    if (grp == 0) {
        float tot = red[k] + red[64 + k] + red[128 + k] + red[192 + k];
        asum[b * K_ + k] = tot;
    }
}

// ---------------- K8: batched VLAD GEMM, h = hi + lo (vectorized loads) ----------------
__global__ void vlad_gemm_kernel(const __nv_bfloat16* __restrict__ hhi,
                                 const __nv_bfloat16* __restrict__ hlo,
                                 const float* __restrict__ actn,
                                 const float* __restrict__ asum, const float* __restrict__ c2,
                                 float* __restrict__ vlad) {
    int b  = blockIdx.x;
    int f0 = blockIdx.y * 64;
    __shared__ float Rs[32][68];
    __shared__ float Qs[32][68];
    int t = threadIdx.x;
    int tx = t & 15, ty = t >> 4;
    float acc[4][4];
    #pragma unroll
    for (int i = 0; i < 4; i++)
        #pragma unroll
        for (int j = 0; j < 4; j++) acc[i][j] = 0.f;

    for (int n0 = 0; n0 < N2_; n0 += 32) {
        __syncthreads();
        #pragma unroll
        for (int i = 0; i < 4; i++) {           // Rs: 1024 bf162 pairs
            int idx = t + i * 256;
            int n = idx >> 5, fp = idx & 31;
            int f = fp * 2;
            int nn = n0 + n;
            int row = b * FR_ + (nn >> 3);
            size_t hidx = (size_t)row * ED_ + (nn & 7) * FEAT_ + f0 + f;
            __nv_bfloat162 hv = *(const __nv_bfloat162*)&hhi[hidx];
            __nv_bfloat162 lv = *(const __nv_bfloat162*)&hlo[hidx];
            Rs[n][f]     = __bfloat162float(hv.x) + __bfloat162float(lv.x);
            Rs[n][f + 1] = __bfloat162float(hv.y) + __bfloat162float(lv.y);
        }
        #pragma unroll
        for (int i = 0; i < 8; i++) {           // Qs: fp32
            int idx = t + i * 256;
            int n = idx >> 6, f = idx & 63;
            int nn = n0 + n;
            int row = b * FR_ + (nn >> 3);
            Qs[n][f] = actn[(size_t)row * (G_ * K_) + (nn & 7) * K_ + f];
        }
        __syncthreads();
        #pragma unroll
        for (int nn = 0; nn < 32; nn++) {
            float rf[4], qf[4];
            *(float4*)rf = *(const float4*)&Rs[nn][ty * 4];
            *(float4*)qf = *(const float4*)&Qs[nn][tx * 4];
            #pragma unroll
            for (int i = 0; i < 4; i++)
                #pragma unroll
                for (int j = 0; j < 4; j++) acc[i][j] += rf[i] * qf[j];
        }
    }
    #pragma unroll
    for (int i = 0; i < 4; i++) {
        int f = f0 + ty * 4 + i;
        #pragma unroll
        for (int j = 0; j < 4; j++) {
            int k = tx * 4 + j;
            float v = acc[i][j] - asum[b * K_ + k] * c2[(size_t)f * K_ + k];
            vlad[((size_t)b * FEAT_ + f) * K_ + k] = v;
        }
    }
}

// ---------------- K9: intra-norm + BN2 ----------------
__global__ void intranorm_bn_kernel(const float* __restrict__ vlad, float* __restrict__ vladn,
                                    const float* __restrict__ g, const float* __restrict__ bb,
                                    const float* __restrict__ mm, const float* __restrict__ vv) {
    int b = blockIdx.x;
    int t = threadIdx.x;
    int k = t & 63, fg = t >> 6;
    float s = 0.f;
    for (int f = fg; f < FEAT_; f += 8) {
        float x = vlad[((size_t)b * FEAT_ + f) * K_ + k];
        s += x * x;
    }
    __shared__ float red[512];
    red[t] = s;
    __syncthreads();
    if (fg == 0) {
        float tot = 0.f;
        #pragma unroll
        for (int i = 0; i < 8; i++) tot += red[i * 64 + k];
        red[k] = 1.f / fmaxf(sqrtf(tot), L2_EPS);
    }
    __syncthreads();
    float inv = red[k];
    for (int f = fg; f < FEAT_; f += 8) {
        int idx = f * K_ + k;
        float x = vlad[((size_t)b * FEAT_ + f) * K_ + k] * inv;
        vladn[(size_t)b * VLAD_ + idx] =
            (x - mm[idx]) * rsqrtf(vv[idx] + BN_EPS) * g[idx] + bb[idx];
    }
}

// ---------------- K10: broadcast bias init ----------------
__global__ void bias_init_kernel(float* __restrict__ C, const float* __restrict__ bias,
                                 int rows, int N) {
    int idx = blockIdx.x * blockDim.x + threadIdx.x;
    if (idx < rows * N) C[idx] = bias[idx % N];
}

// ---------------- K11: skinny GEMM (split-K, atomic) ----------------
__global__ void skinny32_kernel(const float* __restrict__ A, const float* __restrict__ W,
                                float* __restrict__ C, int N, int K, int KC) {
    int o0 = blockIdx.x * 128;
    int k0 = blockIdx.y * KC;
    __shared__ float As[32][36];
    __shared__ float Ws[32][132];
    int t = threadIdx.x;
    int kl = t & 31, rg = t >> 5;
    int oq = t & 31, bq = t >> 5;
    float acc[4][4];
    #pragma unroll
    for (int i = 0; i < 4; i++)
        #pragma unroll
        for (int j = 0; j < 4; j++) acc[i][j] = 0.f;

    int kend = min(k0 + KC, K);
    for (int kt = k0; kt < kend; kt += 32) {
        __syncthreads();
        #pragma unroll
        for (int i = 0; i < 4; i++) {
            int b = rg + i * 8;
            As[kl][b] = A[(size_t)b * K + kt + kl];
        }
        #pragma unroll
        for (int i = 0; i < 16; i++) {
            int o = rg + i * 8;
            int og = o0 + o;
            Ws[kl][o] = (og < N) ? W[(size_t)og * K + kt + kl] : 0.f;
        }
        __syncthreads();
        #pragma unroll
        for (int kk = 0; kk < 32; kk++) {
            float4 w4 = *(const float4*)&Ws[kk][oq * 4];
            float4 a4 = *(const float4*)&As[kk][bq * 4];
            float av[4] = {a4.x, a4.y, a4.z, a4.w};
            float wv[4] = {w4.x, w4.y, w4.z, w4.w};
            #pragma unroll
            for (int i = 0; i < 4; i++)
                #pragma unroll
                for (int j = 0; j < 4; j++) acc[i][j] += av[i] * wv[j];
        }
    }
    #pragma unroll
    for (int i = 0; i < 4; i++) {
        int b = bq * 4 + i;
        #pragma unroll
        for (int j = 0; j < 4; j++) {
            int o = o0 + oq * 4 + j;
            if (o < N) atomicAdd(&C[(size_t)b * N + o], acc[i][j]);
        }
    }
}

// ---------------- K12: BN ----------------
__global__ void bn_kernel(const float* __restrict__ in, float* __restrict__ out,
                          const float* __restrict__ g, const float* __restrict__ bb,
                          const float* __restrict__ mm, const float* __restrict__ vv,
                          int rows, int N) {
    int idx = blockIdx.x * blockDim.x + threadIdx.x;
    if (idx < rows * N) {
        int c = idx % N;
        out[idx] = (in[idx] - mm[c]) * rsqrtf(vv[c] + BN_EPS) * g[c] + bb[c];
    }
}

// ---------------- K13/K14: SE gating ----------------
__global__ void se1_kernel(const float* __restrict__ y, const float* __restrict__ w,
                           const float* __restrict__ bias,
                           const float* __restrict__ g, const float* __restrict__ bb,
                           const float* __restrict__ mm, const float* __restrict__ vv,
                           float* __restrict__ z) {
    int warp = threadIdx.x >> 5, lane = threadIdx.x & 31;
    int idx = blockIdx.x * 8 + warp;
    int b = idx / HR_, o = idx % HR_;
    const float* yr = y + (size_t)b * H_;
    const float* wr = w + (size_t)o * H_;
    float s = 0.f;
    for (int k = lane; k < H_; k += 32) s += yr[k] * wr[k];
    for (int off = 16; off; off >>= 1) s += __shfl_xor_sync(0xffffffffu, s, off);
    if (lane == 0) {
        float v = s + bias[o];
        v = (v - mm[o]) * rsqrtf(vv[o] + BN_EPS) * g[o] + bb[o];
        z[(size_t)b * HR_ + o] = fmaxf(v, 0.f);
    }
}

__global__ void se2_kernel(const float* __restrict__ z, const float* __restrict__ w,
                           const float* __restrict__ bias, const float* __restrict__ y,
                           float* __restrict__ yg) {
    int warp = threadIdx.x >> 5, lane = threadIdx.x & 31;
    int idx = blockIdx.x * 8 + warp;
    int b = idx / H_, o = idx % H_;
    const float* zr = z + (size_t)b * HR_;
    const float* wr = w + (size_t)o * HR_;
    float s = 0.f;
    for (int k = lane; k < HR_; k += 32) s += zr[k] * wr[k];
    for (int off = 16; off; off >>= 1) s += __shfl_xor_sync(0xffffffffu, s, off);
    if (lane == 0) {
        float gate = 1.f / (1.f + expf(-(s + bias[o])));
        yg[(size_t)b * H_ + o] = y[(size_t)b * H_ + o] * gate;
    }
}

// ---------------- host launcher ----------------
extern "C" void kernel_launch(void* const* d_in, const int* in_sizes, int n_in,
                              void* d_out, int out_size) {
    const float* x     = (const float*)d_in[0];
    const float* fc1_w = (const float*)d_in[1];
    const float* fc1_b = (const float*)d_in[2];
    const float* fc2_w = (const float*)d_in[3];
    const float* fc2_b = (const float*)d_in[4];
    const float* c1    = (const float*)d_in[5];
    const float* c2    = (const float*)d_in[6];
    const float* bn1_g = (const float*)d_in[7];
    const float* bn1_b = (const float*)d_in[8];
    const float* bn1_m = (const float*)d_in[9];
    const float* bn1_v = (const float*)d_in[10];
    const float* bn2_g = (const float*)d_in[11];
    const float* bn2_b = (const float*)d_in[12];
    const float* bn2_m = (const float*)d_in[13];
    const float* bn2_v = (const float*)d_in[14];
    const float* cgf_w = (const float*)d_in[15];
    const float* cgf_b = (const float*)d_in[16];
    const float* cgbn_g = (const float*)d_in[17];
    const float* cgbn_b = (const float*)d_in[18];
    const float* cgbn_m = (const float*)d_in[19];
    const float* cgbn_v = (const float*)d_in[20];
    const float* g1_w  = (const float*)d_in[21];
    const float* g1_b  = (const float*)d_in[22];
    const float* gbn_g = (const float*)d_in[23];
    const float* gbn_b = (const float*)d_in[24];
    const float* gbn_m = (const float*)d_in[25];
    const float* gbn_v = (const float*)d_in[26];
    const float* g2_w  = (const float*)d_in[27];
    const float* g2_b  = (const float*)d_in[28];
    const float* fc3_w = (const float*)d_in[29];
    const float* fc3_b = (const float*)d_in[30];
    float* out = (float*)d_out;

    float *rinv, *att, *act, *actn, *asum, *vlad, *vladn, *y0, *y, *z, *yg;
    __nv_bfloat16 *xhi, *xlo, *whi, *wlo, *hhi, *hlo, *c1hi, *c1lo;
    cudaGetSymbolAddress((void**)&rinv,  g_rinv);
    cudaGetSymbolAddress((void**)&att,   g_att);
    cudaGetSymbolAddress((void**)&act,   g_act);
    cudaGetSymbolAddress((void**)&actn,  g_actn);
    cudaGetSymbolAddress((void**)&asum,  g_asum);
    cudaGetSymbolAddress((void**)&vlad,  g_vlad);
    cudaGetSymbolAddress((void**)&vladn, g_vladn);
    cudaGetSymbolAddress((void**)&y0,    g_y0);
    cudaGetSymbolAddress((void**)&y,     g_y);
    cudaGetSymbolAddress((void**)&z,     g_z);
    cudaGetSymbolAddress((void**)&yg,    g_yg);
    cudaGetSymbolAddress((void**)&xhi,   g_xhi);
    cudaGetSymbolAddress((void**)&xlo,   g_xlo);
    cudaGetSymbolAddress((void**)&whi,   g_whi);
    cudaGetSymbolAddress((void**)&wlo,   g_wlo);
    cudaGetSymbolAddress((void**)&hhi,   g_hhi);
    cudaGetSymbolAddress((void**)&hlo,   g_hlo);
    cudaGetSymbolAddress((void**)&c1hi,  g_c1hi);
    cudaGetSymbolAddress((void**)&c1lo,  g_c1lo);

    cudaFuncSetAttribute(mma_gemm_kernel<0>, cudaFuncAttributeMaxDynamicSharedMemorySize, GEMM_SMEM);
    cudaFuncSetAttribute(mma_gemm_kernel<1>, cudaFuncAttributeMaxDynamicSharedMemorySize, GEMM_SMEM);

    // 1. row inverse norms of x
    rownorm_inv_kernel<<<M_, 256>>>(x, rinv);

    // 2. split x (scaled by rinv) and fc1_w into bf16 hi/lo
    split_kernel<<<(M_ * D_ / 4 + 255) / 256, 256>>>(x, xhi, xlo, M_ * D_, rinv, D_);
    split_kernel<<<(ED_ * D_ / 4 + 255) / 256, 256>>>(fc1_w, whi, wlo, ED_ * D_, nullptr, 0);

    // 3. h (bf16 hi/lo only) = xn @ fc1_w^T + fc1_b — tensor cores
    mma_gemm_kernel<0><<<dim3(ED_ / BN, M_ / BM), 256, GEMM_SMEM>>>(
        xhi, xlo, whi, wlo, nullptr, hhi, hlo, M_, ED_, D_, fc1_b, nullptr, nullptr, nullptr);

    // 4. attention
    att_kernel<<<M_, 256>>>(hhi, hlo, fc2_w, fc2_b, att);

    // 5. c1^T + split, fused
    transpose_split_kernel<<<dim3((G_ * K_) / 32, ED_ / 32), 256>>>(c1, c1hi, c1lo, ED_, G_ * K_);

    // 6. act = BN1(h @ c1) — tensor cores
    mma_gemm_kernel<1><<<dim3((G_ * K_) / BN, M_ / BM), 256, GEMM_SMEM>>>(
        hhi, hlo, c1hi, c1lo, act, nullptr, nullptr, M_, G_ * K_, ED_,
        bn1_g, bn1_b, bn1_m, bn1_v);

    // 7. softmax * att
    softmax_att_kernel<<<M_, 256>>>(act, att, actn);

    // 8. asum
    asum_kernel<<<B_, 256>>>(actn, asum);

    // 9. vlad
    vlad_gemm_kernel<<<dim3(B_, FEAT_ / 64), 256>>>(hhi, hlo, actn, asum, c2, vlad);

    // 10. intra-norm + BN2
    intranorm_bn_kernel<<<B_, 512>>>(vlad, vladn, bn2_g, bn2_b, bn2_m, bn2_v);

    // 11. y = BN(vladn @ cgf_w^T + cgf_b)
    bias_init_kernel<<<(B_ * H_ + 255) / 256, 256>>>(y0, cgf_b, B_, H_);
    skinny32_kernel<<<dim3(H_ / 128, 16), 256>>>(vladn, cgf_w, y0, H_, VLAD_, VLAD_ / 16);
    bn_kernel<<<(B_ * H_ + 255) / 256, 256>>>(y0, y, cgbn_g, cgbn_b, cgbn_m, cgbn_v, B_, H_);

    // 12. SE gating
    se1_kernel<<<(B_ * HR_) / 8, 256>>>(y, g1_w, g1_b, gbn_g, gbn_b, gbn_m, gbn_v, z);
    se2_kernel<<<(B_ * H_) / 8, 256>>>(z, g2_w, g2_b, y, yg);

    // 13. out = yg @ fc3_w^T + fc3_b
    bias_init_kernel<<<(B_ * NC_ + 255) / 256, 256>>>(out, fc3_b, B_, NC_);
    skinny32_kernel<<<dim3((NC_ + 127) / 128, 8), 256>>>(yg, fc3_w, out, NC_, H_, H_ / 8);
}

// round 8
// speedup vs baseline: 1.2825x; 1.2247x over previous
#include <cuda_runtime.h>
#include <cuda_fp16.h>
#include <math.h>
#include <stdint.h>

// ---------------- problem constants ----------------
#define B_    32
#define FR_   300
#define D_    2048
#define ED_   4096      // E*D
#define G_    8
#define K_    64
#define FEAT_ 512       // E*D/G
#define VLAD_ 32768     // K*FEAT
#define H_    2048
#define HR_   256       // H/R
#define NC_   3862
#define M_    (B_*FR_)  // 9600
#define N2_   2400      // FR*G
#define BN_EPS 1e-5f
#define L2_EPS 1e-12f

// ---------------- scratch (device globals; no allocs allowed) ----------------
__device__ __align__(128) float g_rinv[M_];
__device__ __align__(128) float g_att[M_ * G_];
__device__ __align__(128) float g_act[M_ * (G_*K_)];
__device__ __align__(128) float g_actn[M_ * (G_*K_)];
__device__ __align__(128) float g_asum[B_ * K_];
__device__ __align__(128) float g_vlad[B_ * FEAT_ * K_];
__device__ __align__(128) float g_vladn[B_ * VLAD_];
__device__ __align__(128) float g_y0[B_ * H_];
__device__ __align__(128) float g_y[B_ * H_];
__device__ __align__(128) float g_z[B_ * HR_];
__device__ __align__(128) float g_yg[B_ * H_];
// fp16 split buffers
__device__ __align__(128) __half g_xh[M_ * D_];
__device__ __align__(128) __half g_wh[ED_ * D_];
__device__ __align__(128) __half g_wl[ED_ * D_];
__device__ __align__(128) __half g_hh[M_ * ED_];
__device__ __align__(128) __half g_hl[M_ * ED_];
__device__ __align__(128) __half g_c1h[(G_*K_) * ED_];
__device__ __align__(128) __half g_c1l[(G_*K_) * ED_];

// ---------------- K1: per-row inverse L2 norm of x ----------------
__global__ void rownorm_inv_kernel(const float* __restrict__ x, float* __restrict__ rinv) {
    int m = blockIdx.x;
    int t = threadIdx.x;
    float s = 0.f;
    const float* row = x + (size_t)m * D_;
    for (int k = t; k < D_; k += 256) { float v = row[k]; s += v * v; }
    for (int o = 16; o; o >>= 1) s += __shfl_xor_sync(0xffffffffu, s, o);
    __shared__ float red[8];
    if ((t & 31) == 0) red[t >> 5] = s;
    __syncthreads();
    if (t == 0) {
        float tot = 0.f;
        #pragma unroll
        for (int i = 0; i < 8; i++) tot += red[i];
        rinv[m] = 1.f / fmaxf(sqrtf(tot), L2_EPS);
    }
}

// ---------------- K2: fp32 -> fp16 hi (+ optional lo), optional row scale ----------------
__global__ void split_half_kernel(const float* __restrict__ src,
                                  __half* __restrict__ hi, __half* __restrict__ lo,
                                  int n, const float* __restrict__ rowscale, int rowlen) {
    int i = (blockIdx.x * blockDim.x + threadIdx.x) * 4;
    if (i >= n) return;
    float4 v = *(const float4*)(src + i);
    if (rowscale) {
        float s = rowscale[i / rowlen];
        v.x *= s; v.y *= s; v.z *= s; v.w *= s;
    }
    __half h0 = __float2half_rn(v.x), h1 = __float2half_rn(v.y);
    __half h2 = __float2half_rn(v.z), h3 = __float2half_rn(v.w);
    __half2 a; a.x = h0; a.y = h1;
    __half2 b; b.x = h2; b.y = h3;
    *(__half2*)&hi[i]     = a;
    *(__half2*)&hi[i + 2] = b;
    if (lo) {
        a.x = __float2half_rn(v.x - __half2float(h0));
        a.y = __float2half_rn(v.y - __half2float(h1));
        b.x = __float2half_rn(v.z - __half2float(h2));
        b.y = __float2half_rn(v.w - __half2float(h3));
        *(__half2*)&lo[i]     = a;
        *(__half2*)&lo[i + 2] = b;
    }
}

// ---------------- K2b: fused transpose + fp16 split: c1[R,C] -> c1h/l[C,R] ----------------
__global__ void transpose_split_kernel(const float* __restrict__ in,
                                       __half* __restrict__ hi,
                                       __half* __restrict__ lo, int R, int C) {
    __shared__ float tile[32][33];
    int c0 = blockIdx.x * 32, r0 = blockIdx.y * 32;
    int tx = threadIdx.x & 31, ty = threadIdx.x >> 5;   // 256 thr
    #pragma unroll
    for (int i = 0; i < 32; i += 8)
        tile[ty + i][tx] = in[(size_t)(r0 + ty + i) * C + c0 + tx];
    __syncthreads();
    #pragma unroll
    for (int i = 0; i < 32; i += 8) {
        float v = tile[tx][ty + i];
        __half hv = __float2half_rn(v);
        size_t idx = (size_t)(c0 + ty + i) * R + r0 + tx;
        hi[idx] = hv;
        lo[idx] = __float2half_rn(v - __half2float(hv));
    }
}

// ---------------- tensor-core GEMM: C[M,N] = A[M,K] * B[N,K]^T  (fp16 split) -----------
// BK=32, 2 stages.  PASSES=2: A single (ah), B pair -> 2 MMAs/tile.
//                   PASSES=3: A pair, B pair -> 3 MMAs/tile.
#define BM 128
#define BN 128
#define BKK 32
#define SSTRIDE 40                        // BKK + 8
#define MAT_BYTES (128 * SSTRIDE * 2)     // 10240

__device__ __forceinline__ void cp16(uint32_t dst, const void* src) {
    asm volatile("cp.async.cg.shared.global [%0], [%1], 16;\n" :: "r"(dst), "l"(src));
}
__device__ __forceinline__ void ldsm_x4(uint32_t& r0, uint32_t& r1, uint32_t& r2, uint32_t& r3,
                                        uint32_t addr) {
    asm volatile("ldmatrix.sync.aligned.m8n8.x4.shared.b16 {%0,%1,%2,%3}, [%4];\n"
                 : "=r"(r0), "=r"(r1), "=r"(r2), "=r"(r3) : "r"(addr));
}
__device__ __forceinline__ void mma16816(float* c, const uint32_t* a, const uint32_t* b) {
    asm volatile("mma.sync.aligned.m16n8k16.row.col.f32.f16.f16.f32 "
                 "{%0,%1,%2,%3},{%4,%5,%6,%7},{%8,%9},{%0,%1,%2,%3};\n"
                 : "+f"(c[0]), "+f"(c[1]), "+f"(c[2]), "+f"(c[3])
                 : "r"(a[0]), "r"(a[1]), "r"(a[2]), "r"(a[3]), "r"(b[0]), "r"(b[1]));
}

// MODE 0: emit Chi/Clo = fp16 split of (acc + p0[n])
// MODE 1: emit C fp32 = (acc - p2[n])*rsqrt(p3[n]+eps)*p0[n] + p1[n]
template <int MODE, int PASSES>
__global__ __launch_bounds__(256, 2)
void mma_gemm_kernel(const __half* __restrict__ Ahi, const __half* __restrict__ Alo,
                     const __half* __restrict__ Bhi, const __half* __restrict__ Blo,
                     float* __restrict__ C, __half* __restrict__ Chi,
                     __half* __restrict__ Clo, int M, int N, int K,
                     const float* __restrict__ p0, const float* __restrict__ p1,
                     const float* __restrict__ p2, const float* __restrict__ p3) {
    constexpr int NMAT = PASSES + 1;              // matrices per stage
    constexpr int BHI = (PASSES == 3) ? 2 : 1;    // B-hi matrix index
    constexpr uint32_t STAGE_B = NMAT * MAT_BYTES;

    extern __shared__ __align__(16) unsigned char smem_raw[];
    uint32_t sbase = (uint32_t)__cvta_generic_to_shared(smem_raw);

    const int t = threadIdx.x;
    const int lane = t & 31;
    const int warp = t >> 5;
    const int wy = warp >> 2;       // 0..1 (M)
    const int wx = warp & 3;        // 0..3 (N)
    const int m0 = blockIdx.y * BM;
    const int n0 = blockIdx.x * BN;

    float acc[4][4][4];
    #pragma unroll
    for (int i = 0; i < 4; i++)
        #pragma unroll
        for (int j = 0; j < 4; j++)
            #pragma unroll
            for (int q = 0; q < 4; q++) acc[i][j][q] = 0.f;

    const __half* msrc[NMAT];
    msrc[0] = Ahi;
    if (PASSES == 3) { msrc[1] = Alo; msrc[2] = Bhi; msrc[3] = Blo; }
    else             { msrc[1] = Bhi; msrc[2] = Blo; }

    // loader: 512 16B-chunks per 128x32 matrix; chunk c: row=c>>2, seg=c&3
    auto issue = [&](int chunk, int buf) {
        uint32_t sb = sbase + buf * STAGE_B;
        int kpos = chunk * BKK;
        #pragma unroll
        for (int i = 0; i < NMAT * 2; i++) {
            constexpr_helper:;
            int mat = i >> 1;                       // compile-time per unrolled i
            int c = (i & 1) * 256 + t;              // 0..511
            int row = c >> 2, seg = c & 3;
            uint32_t so = (uint32_t)(row * SSTRIDE + seg * 8) * 2 + (uint32_t)mat * MAT_BYTES;
            bool isA = (mat < BHI);
            size_t g = (size_t)((isA ? m0 : n0) + row) * K + kpos + seg * 8;
            cp16(sb + so, msrc[mat] + g);
        }
        asm volatile("cp.async.commit_group;\n");
    };

    const uint32_t aOff = (uint32_t)((wy * 64 + (lane & 15)) * SSTRIDE + ((lane >> 4) * 8)) * 2;
    const uint32_t bOff = (uint32_t)((wx * 32 + ((lane >> 4) * 8) + (lane & 7)) * SSTRIDE
                                     + (((lane >> 3) & 1) * 8)) * 2;

    const int NK = K / BKK;
    issue(0, 0);

    for (int kt = 0; kt < NK; kt++) {
        if (kt + 1 < NK) {
            issue(kt + 1, (kt + 1) & 1);
            asm volatile("cp.async.wait_group 1;\n" ::: "memory");
        } else {
            asm volatile("cp.async.wait_group 0;\n" ::: "memory");
        }
        __syncthreads();
        uint32_t sb = sbase + (kt & 1) * STAGE_B;
        #pragma unroll
        for (int kk = 0; kk < BKK / 16; kk++) {
            uint32_t kby = (uint32_t)(kk * 16) * 2;
            uint32_t ahi[4][4], alo[4][4], bhi[4][2], blo[4][2];
            #pragma unroll
            for (int mt = 0; mt < 4; mt++) {
                uint32_t ad = sb + aOff + kby + (uint32_t)(mt * 16 * SSTRIDE) * 2;
                ldsm_x4(ahi[mt][0], ahi[mt][1], ahi[mt][2], ahi[mt][3], ad);
                if (PASSES == 3)
                    ldsm_x4(alo[mt][0], alo[mt][1], alo[mt][2], alo[mt][3], ad + MAT_BYTES);
            }
            #pragma unroll
            for (int p = 0; p < 2; p++) {
                uint32_t bd = sb + BHI * MAT_BYTES + bOff + kby
                              + (uint32_t)(p * 16 * SSTRIDE) * 2;
                uint32_t r0, r1, r2, r3;
                ldsm_x4(r0, r1, r2, r3, bd);
                bhi[p * 2][0] = r0; bhi[p * 2][1] = r1;
                bhi[p * 2 + 1][0] = r2; bhi[p * 2 + 1][1] = r3;
                ldsm_x4(r0, r1, r2, r3, bd + MAT_BYTES);
                blo[p * 2][0] = r0; blo[p * 2][1] = r1;
                blo[p * 2 + 1][0] = r2; blo[p * 2 + 1][1] = r3;
            }
            #pragma unroll
            for (int mt = 0; mt < 4; mt++)
                #pragma unroll
                for (int nt = 0; nt < 4; nt++) {
                    mma16816(acc[mt][nt], ahi[mt], bhi[nt]);
                    mma16816(acc[mt][nt], ahi[mt], blo[nt]);
                    if (PASSES == 3) mma16816(acc[mt][nt], alo[mt], bhi[nt]);
                }
        }
        __syncthreads();
    }

    // epilogue
    #pragma unroll
    for (int mt = 0; mt < 4; mt++) {
        int r = m0 + wy * 64 + mt * 16 + (lane >> 2);
        #pragma unroll
        for (int nt = 0; nt < 4; nt++) {
            int c = n0 + wx * 32 + nt * 8 + (lane & 3) * 2;
            float v00 = acc[mt][nt][0], v01 = acc[mt][nt][1];
            float v10 = acc[mt][nt][2], v11 = acc[mt][nt][3];
            if (MODE == 0) {
                float b0 = p0[c], b1 = p0[c + 1];
                v00 += b0; v01 += b1; v10 += b0; v11 += b1;
                __half h00 = __float2half_rn(v00), h01 = __float2half_rn(v01);
                __half h10 = __float2half_rn(v10), h11 = __float2half_rn(v11);
                __half2 hh;
                hh.x = h00; hh.y = h01; *(__half2*)&Chi[(size_t)r * N + c] = hh;
                hh.x = h10; hh.y = h11; *(__half2*)&Chi[(size_t)(r + 8) * N + c] = hh;
                __half2 ll;
                ll.x = __float2half_rn(v00 - __half2float(h00));
                ll.y = __float2half_rn(v01 - __half2float(h01));
                *(__half2*)&Clo[(size_t)r * N + c] = ll;
                ll.x = __float2half_rn(v10 - __half2float(h10));
                ll.y = __float2half_rn(v11 - __half2float(h11));
                *(__half2*)&Clo[(size_t)(r + 8) * N + c] = ll;
            } else {
                float s0 = rsqrtf(p3[c] + BN_EPS) * p0[c];
                float s1 = rsqrtf(p3[c + 1] + BN_EPS) * p0[c + 1];
                float t0 = p1[c] - p2[c] * s0;
                float t1 = p1[c + 1] - p2[c + 1] * s1;
                float2 o0 = {v00 * s0 + t0, v01 * s1 + t1};
                float2 o1 = {v10 * s0 + t0, v11 * s1 + t1};
                *(float2*)&C[(size_t)r * N + c] = o0;
                *(float2*)&C[(size_t)(r + 8) * N + c] = o1;
            }
        }
    }
}

// ---------------- K3: attention = sigmoid(h @ fc2_w^T + b), h = hi + lo ----------------
__global__ void att_kernel(const __half* __restrict__ hh,
                           const __half* __restrict__ hl,
                           const float* __restrict__ w2,
                           const float* __restrict__ b2, float* __restrict__ att) {
    int m = blockIdx.x;
    int warp = threadIdx.x >> 5, lane = threadIdx.x & 31;
    const __half* hr = hh + (size_t)m * ED_;
    const __half* lr = hl + (size_t)m * ED_;
    const float* wr = w2 + (size_t)warp * ED_;
    float s = 0.f;
    for (int k = lane * 2; k < ED_; k += 64) {
        float2 a = __half22float2(*(const __half2*)&hr[k]);
        float2 b = __half22float2(*(const __half2*)&lr[k]);
        float2 w = *(const float2*)&wr[k];
        s += (a.x + b.x) * w.x + (a.y + b.y) * w.y;
    }
    for (int o = 16; o; o >>= 1) s += __shfl_xor_sync(0xffffffffu, s, o);
    if (lane == 0) {
        float v = s + b2[warp];
        att[m * G_ + warp] = 1.f / (1.f + expf(-v));
    }
}

// ---------------- K6: softmax over K within each group, times attention ----------------
__global__ void softmax_att_kernel(const float* __restrict__ act, const float* __restrict__ att,
                                   float* __restrict__ actn) {
    int m = blockIdx.x;
    int g = threadIdx.x >> 5, lane = threadIdx.x & 31;
    const float* row = act + (size_t)m * (G_ * K_) + g * K_;
    float v0 = row[lane], v1 = row[lane + 32];
    float mx = fmaxf(v0, v1);
    for (int o = 16; o; o >>= 1) mx = fmaxf(mx, __shfl_xor_sync(0xffffffffu, mx, o));
    float e0 = expf(v0 - mx), e1 = expf(v1 - mx);
    float s = e0 + e1;
    for (int o = 16; o; o >>= 1) s += __shfl_xor_sync(0xffffffffu, s, o);
    float scl = att[m * G_ + g] / s;
    float* orow = actn + (size_t)m * (G_ * K_) + g * K_;
    orow[lane] = e0 * scl;
    orow[lane + 32] = e1 * scl;
}

// ---------------- K7: asum[b,k] ----------------
__global__ void asum_kernel(const float* __restrict__ actn, float* __restrict__ asum) {
    int b = blockIdx.x;
    int t = threadIdx.x;
    int k = t & 63, grp = t >> 6;
    float s = 0.f;
    for (int n = grp; n < N2_; n += 4) {
        int row = b * FR_ + (n >> 3);
        s += actn[(size_t)row * (G_ * K_) + (n & 7) * K_ + k];
    }
    __shared__ float red[256];
    red[t] = s;
    __syncthreads();
    if (grp == 0) {
        float tot = red[k] + red[64 + k] + red[128 + k] + red[192 + k];
        asum[b * K_ + k] = tot;
    }
}

// ---------------- K8: batched VLAD GEMM, h = hi + lo ----------------
__global__ void vlad_gemm_kernel(const __half* __restrict__ hh,
                                 const __half* __restrict__ hl,
                                 const float* __restrict__ actn,
                                 const float* __restrict__ asum, const float* __restrict__ c2,
                                 float* __restrict__ vlad) {
    int b  = blockIdx.x;
    int f0 = blockIdx.y * 64;
    __shared__ float Rs[32][68];
    __shared__ float Qs[32][68];
    int t = threadIdx.x;
    int tx = t & 15, ty = t >> 4;
    float acc[4][4];
    #pragma unroll
    for (int i = 0; i < 4; i++)
        #pragma unroll
        for (int j = 0; j < 4; j++) acc[i][j] = 0.f;

    for (int n0 = 0; n0 < N2_; n0 += 32) {
        __syncthreads();
        #pragma unroll
        for (int i = 0; i < 4; i++) {           // Rs: half2 pairs
            int idx = t + i * 256;
            int n = idx >> 5, fp = idx & 31;
            int f = fp * 2;
            int nn = n0 + n;
            int row = b * FR_ + (nn >> 3);
            size_t hidx = (size_t)row * ED_ + (nn & 7) * FEAT_ + f0 + f;
            float2 hv = __half22float2(*(const __half2*)&hh[hidx]);
            float2 lv = __half22float2(*(const __half2*)&hl[hidx]);
            Rs[n][f]     = hv.x + lv.x;
            Rs[n][f + 1] = hv.y + lv.y;
        }
        #pragma unroll
        for (int i = 0; i < 8; i++) {           // Qs: fp32
            int idx = t + i * 256;
            int n = idx >> 6, f = idx & 63;
            int nn = n0 + n;
            int row = b * FR_ + (nn >> 3);
            Qs[n][f] = actn[(size_t)row * (G_ * K_) + (nn & 7) * K_ + f];
        }
        __syncthreads();
        #pragma unroll
        for (int nn = 0; nn < 32; nn++) {
            float rf[4], qf[4];
            *(float4*)rf = *(const float4*)&Rs[nn][ty * 4];
            *(float4*)qf = *(const float4*)&Qs[nn][tx * 4];
            #pragma unroll
            for (int i = 0; i < 4; i++)
                #pragma unroll
                for (int j = 0; j < 4; j++) acc[i][j] += rf[i] * qf[j];
        }
    }
    #pragma unroll
    for (int i = 0; i < 4; i++) {
        int f = f0 + ty * 4 + i;
        #pragma unroll
        for (int j = 0; j < 4; j++) {
            int k = tx * 4 + j;
            float v = acc[i][j] - asum[b * K_ + k] * c2[(size_t)f * K_ + k];
            vlad[((size_t)b * FEAT_ + f) * K_ + k] = v;
        }
    }
}

// ---------------- K9: intra-norm + BN2 ----------------
__global__ void intranorm_bn_kernel(const float* __restrict__ vlad, float* __restrict__ vladn,
                                    const float* __restrict__ g, const float* __restrict__ bb,
                                    const float* __restrict__ mm, const float* __restrict__ vv) {
    int b = blockIdx.x;
    int t = threadIdx.x;
    int k = t & 63, fg = t >> 6;
    float s = 0.f;
    for (int f = fg; f < FEAT_; f += 8) {
        float x = vlad[((size_t)b * FEAT_ + f) * K_ + k];
        s += x * x;
    }
    __shared__ float red[512];
    red[t] = s;
    __syncthreads();
    if (fg == 0) {
        float tot = 0.f;
        #pragma unroll
        for (int i = 0; i < 8; i++) tot += red[i * 64 + k];
        red[k] = 1.f / fmaxf(sqrtf(tot), L2_EPS);
    }
    __syncthreads();
    float inv = red[k];
    for (int f = fg; f < FEAT_; f += 8) {
        int idx = f * K_ + k;
        float x = vlad[((size_t)b * FEAT_ + f) * K_ + k] * inv;
        vladn[(size_t)b * VLAD_ + idx] =
            (x - mm[idx]) * rsqrtf(vv[idx] + BN_EPS) * g[idx] + bb[idx];
    }
}

// ---------------- K10: broadcast bias init ----------------
__global__ void bias_init_kernel(float* __restrict__ C, const float* __restrict__ bias,
                                 int rows, int N) {
    int idx = blockIdx.x * blockDim.x + threadIdx.x;
    if (idx < rows * N) C[idx] = bias[idx % N];
}

// ---------------- K11: skinny GEMM (split-K, atomic) ----------------
__global__ void skinny32_kernel(const float* __restrict__ A, const float* __restrict__ W,
                                float* __restrict__ C, int N, int K, int KC) {
    int o0 = blockIdx.x * 128;
    int k0 = blockIdx.y * KC;
    __shared__ float As[32][36];
    __shared__ float Ws[32][132];
    int t = threadIdx.x;
    int kl = t & 31, rg = t >> 5;
    int oq = t & 31, bq = t >> 5;
    float acc[4][4];
    #pragma unroll
    for (int i = 0; i < 4; i++)
        #pragma unroll
        for (int j = 0; j < 4; j++) acc[i][j] = 0.f;

    int kend = min(k0 + KC, K);
    for (int kt = k0; kt < kend; kt += 32) {
        __syncthreads();
        #pragma unroll
        for (int i = 0; i < 4; i++) {
            int b = rg + i * 8;
            As[kl][b] = A[(size_t)b * K + kt + kl];
        }
        #pragma unroll
        for (int i = 0; i < 16; i++) {
            int o = rg + i * 8;
            int og = o0 + o;
            Ws[kl][o] = (og < N) ? W[(size_t)og * K + kt + kl] : 0.f;
        }
        __syncthreads();
        #pragma unroll
        for (int kk = 0; kk < 32; kk++) {
            float4 w4 = *(const float4*)&Ws[kk][oq * 4];
            float4 a4 = *(const float4*)&As[kk][bq * 4];
            float av[4] = {a4.x, a4.y, a4.z, a4.w};
            float wv[4] = {w4.x, w4.y, w4.z, w4.w};
            #pragma unroll
            for (int i = 0; i < 4; i++)
                #pragma unroll
                for (int j = 0; j < 4; j++) acc[i][j] += av[i] * wv[j];
        }
    }
    #pragma unroll
    for (int i = 0; i < 4; i++) {
        int b = bq * 4 + i;
        #pragma unroll
        for (int j = 0; j < 4; j++) {
            int o = o0 + oq * 4 + j;
            if (o < N) atomicAdd(&C[(size_t)b * N + o], acc[i][j]);
        }
    }
}

// ---------------- K12: BN ----------------
__global__ void bn_kernel(const float* __restrict__ in, float* __restrict__ out,
                          const float* __restrict__ g, const float* __restrict__ bb,
                          const float* __restrict__ mm, const float* __restrict__ vv,
                          int rows, int N) {
    int idx = blockIdx.x * blockDim.x + threadIdx.x;
    if (idx < rows * N) {
        int c = idx % N;
        out[idx] = (in[idx] - mm[c]) * rsqrtf(vv[c] + BN_EPS) * g[c] + bb[c];
    }
}

// ---------------- K13/K14: SE gating ----------------
__global__ void se1_kernel(const float* __restrict__ y, const float* __restrict__ w,
                           const float* __restrict__ bias,
                           const float* __restrict__ g, const float* __restrict__ bb,
                           const float* __restrict__ mm, const float* __restrict__ vv,
                           float* __restrict__ z) {
    int warp = threadIdx.x >> 5, lane = threadIdx.x & 31;
    int idx = blockIdx.x * 8 + warp;
    int b = idx / HR_, o = idx % HR_;
    const float* yr = y + (size_t)b * H_;
    const float* wr = w + (size_t)o * H_;
    float s = 0.f;
    for (int k = lane; k < H_; k += 32) s += yr[k] * wr[k];
    for (int off = 16; off; off >>= 1) s += __shfl_xor_sync(0xffffffffu, s, off);
    if (lane == 0) {
        float v = s + bias[o];
        v = (v - mm[o]) * rsqrtf(vv[o] + BN_EPS) * g[o] + bb[o];
        z[(size_t)b * HR_ + o] = fmaxf(v, 0.f);
    }
}

__global__ void se2_kernel(const float* __restrict__ z, const float* __restrict__ w,
                           const float* __restrict__ bias, const float* __restrict__ y,
                           float* __restrict__ yg) {
    int warp = threadIdx.x >> 5, lane = threadIdx.x & 31;
    int idx = blockIdx.x * 8 + warp;
    int b = idx / H_, o = idx % H_;
    const float* zr = z + (size_t)b * HR_;
    const float* wr = w + (size_t)o * HR_;
    float s = 0.f;
    for (int k = lane; k < HR_; k += 32) s += zr[k] * wr[k];
    for (int off = 16; off; off >>= 1) s += __shfl_xor_sync(0xffffffffu, s, off);
    if (lane == 0) {
        float gate = 1.f / (1.f + expf(-(s + bias[o])));
        yg[(size_t)b * H_ + o] = y[(size_t)b * H_ + o] * gate;
    }
}

// ---------------- host launcher ----------------
extern "C" void kernel_launch(void* const* d_in, const int* in_sizes, int n_in,
                              void* d_out, int out_size) {
    const float* x     = (const float*)d_in[0];
    const float* fc1_w = (const float*)d_in[1];
    const float* fc1_b = (const float*)d_in[2];
    const float* fc2_w = (const float*)d_in[3];
    const float* fc2_b = (const float*)d_in[4];
    const float* c1    = (const float*)d_in[5];
    const float* c2    = (const float*)d_in[6];
    const float* bn1_g = (const float*)d_in[7];
    const float* bn1_b = (const float*)d_in[8];
    const float* bn1_m = (const float*)d_in[9];
    const float* bn1_v = (const float*)d_in[10];
    const float* bn2_g = (const float*)d_in[11];
    const float* bn2_b = (const float*)d_in[12];
    const float* bn2_m = (const float*)d_in[13];
    const float* bn2_v = (const float*)d_in[14];
    const float* cgf_w = (const float*)d_in[15];
    const float* cgf_b = (const float*)d_in[16];
    const float* cgbn_g = (const float*)d_in[17];
    const float* cgbn_b = (const float*)d_in[18];
    const float* cgbn_m = (const float*)d_in[19];
    const float* cgbn_v = (const float*)d_in[20];
    const float* g1_w  = (const float*)d_in[21];
    const float* g1_b  = (const float*)d_in[22];
    const float* gbn_g = (const float*)d_in[23];
    const float* gbn_b = (const float*)d_in[24];
    const float* gbn_m = (const float*)d_in[25];
    const float* gbn_v = (const float*)d_in[26];
    const float* g2_w  = (const float*)d_in[27];
    const float* g2_b  = (const float*)d_in[28];
    const float* fc3_w = (const float*)d_in[29];
    const float* fc3_b = (const float*)d_in[30];
    float* out = (float*)d_out;

    float *rinv, *att, *act, *actn, *asum, *vlad, *vladn, *y0, *y, *z, *yg;
    __half *xh, *wh, *wl, *hh, *hl, *c1h, *c1l;
    cudaGetSymbolAddress((void**)&rinv,  g_rinv);
    cudaGetSymbolAddress((void**)&att,   g_att);
    cudaGetSymbolAddress((void**)&act,   g_act);
    cudaGetSymbolAddress((void**)&actn,  g_actn);
    cudaGetSymbolAddress((void**)&asum,  g_asum);
    cudaGetSymbolAddress((void**)&vlad,  g_vlad);
    cudaGetSymbolAddress((void**)&vladn, g_vladn);
    cudaGetSymbolAddress((void**)&y0,    g_y0);
    cudaGetSymbolAddress((void**)&y,     g_y);
    cudaGetSymbolAddress((void**)&z,     g_z);
    cudaGetSymbolAddress((void**)&yg,    g_yg);
    cudaGetSymbolAddress((void**)&xh,    g_xh);
    cudaGetSymbolAddress((void**)&wh,    g_wh);
    cudaGetSymbolAddress((void**)&wl,    g_wl);
    cudaGetSymbolAddress((void**)&hh,    g_hh);
    cudaGetSymbolAddress((void**)&hl,    g_hl);
    cudaGetSymbolAddress((void**)&c1h,   g_c1h);
    cudaGetSymbolAddress((void**)&c1l,   g_c1l);

    const int SMEM2 = 2 * 3 * MAT_BYTES;   // PASSES=2: 61440
    const int SMEM3 = 2 * 4 * MAT_BYTES;   // PASSES=3: 81920
    cudaFuncSetAttribute((const void*)mma_gemm_kernel<0, 2>,
                         cudaFuncAttributeMaxDynamicSharedMemorySize, SMEM2);
    cudaFuncSetAttribute((const void*)mma_gemm_kernel<1, 3>,
                         cudaFuncAttributeMaxDynamicSharedMemorySize, SMEM3);

    // 1. row inverse norms of x
    rownorm_inv_kernel<<<M_, 256>>>(x, rinv);

    // 2. x -> fp16 (scaled, hi only); fc1_w -> fp16 hi/lo
    split_half_kernel<<<(M_ * D_ / 4 + 255) / 256, 256>>>(x, xh, nullptr, M_ * D_, rinv, D_);
    split_half_kernel<<<(ED_ * D_ / 4 + 255) / 256, 256>>>(fc1_w, wh, wl, ED_ * D_, nullptr, 0);

    // 3. h (fp16 hi/lo) = xn @ fc1_w^T + fc1_b — 2-pass fp16 tensor cores
    mma_gemm_kernel<0, 2><<<dim3(ED_ / BN, M_ / BM), 256, SMEM2>>>(
        xh, nullptr, wh, wl, nullptr, hh, hl, M_, ED_, D_, fc1_b, nullptr, nullptr, nullptr);

    // 4. attention
    att_kernel<<<M_, 256>>>(hh, hl, fc2_w, fc2_b, att);

    // 5. c1^T + fp16 split, fused
    transpose_split_kernel<<<dim3((G_ * K_) / 32, ED_ / 32), 256>>>(c1, c1h, c1l, ED_, G_ * K_);

    // 6. act = BN1(h @ c1) — 3-pass fp16 tensor cores
    mma_gemm_kernel<1, 3><<<dim3((G_ * K_) / BN, M_ / BM), 256, SMEM3>>>(
        hh, hl, c1h, c1l, act, nullptr, nullptr, M_, G_ * K_, ED_,
        bn1_g, bn1_b, bn1_m, bn1_v);

    // 7. softmax * att
    softmax_att_kernel<<<M_, 256>>>(act, att, actn);

    // 8. asum
    asum_kernel<<<B_, 256>>>(actn, asum);

    // 9. vlad
    vlad_gemm_kernel<<<dim3(B_, FEAT_ / 64), 256>>>(hh, hl, actn, asum, c2, vlad);

    // 10. intra-norm + BN2
    intranorm_bn_kernel<<<B_, 512>>>(vlad, vladn, bn2_g, bn2_b, bn2_m, bn2_v);

    // 11. y = BN(vladn @ cgf_w^T + cgf_b)
    bias_init_kernel<<<(B_ * H_ + 255) / 256, 256>>>(y0, cgf_b, B_, H_);
    skinny32_kernel<<<dim3(H_ / 128, 16), 256>>>(vladn, cgf_w, y0, H_, VLAD_, VLAD_ / 16);
    bn_kernel<<<(B_ * H_ + 255) / 256, 256>>>(y0, y, cgbn_g, cgbn_b, cgbn_m, cgbn_v, B_, H_);

    // 12. SE gating
    se1_kernel<<<(B_ * HR_) / 8, 256>>>(y, g1_w, g1_b, gbn_g, gbn_b, gbn_m, gbn_v, z);
    se2_kernel<<<(B_ * H_) / 8, 256>>>(z, g2_w, g2_b, y, yg);

    // 13. out = yg @ fc3_w^T + fc3_b
    bias_init_kernel<<<(B_ * NC_ + 255) / 256, 256>>>(out, fc3_b, B_, NC_);
    skinny32_kernel<<<dim3((NC_ + 127) / 128, 8), 256>>>(yg, fc3_w, out, NC_, H_, H_ / 8);
}

// round 9
// speedup vs baseline: 1.7150x; 1.3372x over previous
#include <cuda_runtime.h>
#include <cuda_fp16.h>
#include <math.h>
#include <stdint.h>

// ---------------- problem constants ----------------
#define B_    32
#define FR_   300
#define D_    2048
#define ED_   4096      // E*D
#define G_    8
#define K_    64
#define FEAT_ 512       // E*D/G
#define VLAD_ 32768     // K*FEAT
#define H_    2048
#define HR_   256       // H/R
#define NC_   3862
#define M_    (B_*FR_)  // 9600
#define N2_   2400      // FR*G
#define BN_EPS 1e-5f
#define L2_EPS 1e-12f

// ---------------- scratch (device globals; no allocs allowed) ----------------
__device__ __align__(128) float g_rinv[M_];
__device__ __align__(128) float g_att[M_ * G_];
__device__ __align__(128) float g_act[M_ * (G_*K_)];
__device__ __align__(128) float g_actn[M_ * (G_*K_)];
__device__ __align__(128) float g_asum[B_ * K_];
__device__ __align__(128) float g_vlad[B_ * FEAT_ * K_];
__device__ __align__(128) float g_vladn[B_ * VLAD_];
__device__ __align__(128) float g_y0[B_ * H_];
__device__ __align__(128) float g_y[B_ * H_];
__device__ __align__(128) float g_z[B_ * HR_];
__device__ __align__(128) float g_yg[B_ * H_];
// fp16 buffers
__device__ __align__(128) __half g_xh[M_ * D_];
__device__ __align__(128) __half g_wh[ED_ * D_];
__device__ __align__(128) __half g_hh[M_ * ED_];
__device__ __align__(128) __half g_c1h[(G_*K_) * ED_];
__device__ __align__(128) __half g_c1l[(G_*K_) * ED_];

// ---------------- K1: per-row inverse L2 norm of x ----------------
__global__ void rownorm_inv_kernel(const float* __restrict__ x, float* __restrict__ rinv) {
    int m = blockIdx.x;
    int t = threadIdx.x;
    float s = 0.f;
    const float* row = x + (size_t)m * D_;
    for (int k = t; k < D_; k += 256) { float v = row[k]; s += v * v; }
    for (int o = 16; o; o >>= 1) s += __shfl_xor_sync(0xffffffffu, s, o);
    __shared__ float red[8];
    if ((t & 31) == 0) red[t >> 5] = s;
    __syncthreads();
    if (t == 0) {
        float tot = 0.f;
        #pragma unroll
        for (int i = 0; i < 8; i++) tot += red[i];
        rinv[m] = 1.f / fmaxf(sqrtf(tot), L2_EPS);
    }
}

// ---------------- K2: fp32 -> fp16 (single), optional row scale ----------------
__global__ void tohalf_kernel(const float* __restrict__ src, __half* __restrict__ dst,
                              int n, const float* __restrict__ rowscale, int rowlen) {
    int i = (blockIdx.x * blockDim.x + threadIdx.x) * 4;
    if (i >= n) return;
    float4 v = *(const float4*)(src + i);
    if (rowscale) {
        float s = rowscale[i / rowlen];
        v.x *= s; v.y *= s; v.z *= s; v.w *= s;
    }
    __half2 a; a.x = __float2half_rn(v.x); a.y = __float2half_rn(v.y);
    __half2 b; b.x = __float2half_rn(v.z); b.y = __float2half_rn(v.w);
    *(__half2*)&dst[i]     = a;
    *(__half2*)&dst[i + 2] = b;
}

// ---------------- K2b: fused transpose + fp16 split: c1[R,C] -> c1h/l[C,R] ----------------
__global__ void transpose_split_kernel(const float* __restrict__ in,
                                       __half* __restrict__ hi,
                                       __half* __restrict__ lo, int R, int C) {
    __shared__ float tile[32][33];
    int c0 = blockIdx.x * 32, r0 = blockIdx.y * 32;
    int tx = threadIdx.x & 31, ty = threadIdx.x >> 5;   // 256 thr
    #pragma unroll
    for (int i = 0; i < 32; i += 8)
        tile[ty + i][tx] = in[(size_t)(r0 + ty + i) * C + c0 + tx];
    __syncthreads();
    #pragma unroll
    for (int i = 0; i < 32; i += 8) {
        float v = tile[tx][ty + i];
        __half hv = __float2half_rn(v);
        size_t idx = (size_t)(c0 + ty + i) * R + r0 + tx;
        hi[idx] = hv;
        lo[idx] = __float2half_rn(v - __half2float(hv));
    }
}

// ---------------- tensor-core GEMM: C[M,N] = A[M,K] * B[N,K]^T  (fp16) -----------------
// BK=32, 2 stages.  PASSES=1: A single, B single (1 MMA/tile).
//                   PASSES=2: A single, B hi/lo  (2 MMAs/tile).
#define BM 128
#define BN 128
#define BKK 32
#define SSTRIDE 40                        // BKK + 8
#define MAT_BYTES (128 * SSTRIDE * 2)     // 10240

__device__ __forceinline__ void cp16(uint32_t dst, const void* src) {
    asm volatile("cp.async.cg.shared.global [%0], [%1], 16;\n" :: "r"(dst), "l"(src));
}
__device__ __forceinline__ void ldsm_x4(uint32_t& r0, uint32_t& r1, uint32_t& r2, uint32_t& r3,
                                        uint32_t addr) {
    asm volatile("ldmatrix.sync.aligned.m8n8.x4.shared.b16 {%0,%1,%2,%3}, [%4];\n"
                 : "=r"(r0), "=r"(r1), "=r"(r2), "=r"(r3) : "r"(addr));
}
__device__ __forceinline__ void mma16816(float* c, const uint32_t* a, const uint32_t* b) {
    asm volatile("mma.sync.aligned.m16n8k16.row.col.f32.f16.f16.f32 "
                 "{%0,%1,%2,%3},{%4,%5,%6,%7},{%8,%9},{%0,%1,%2,%3};\n"
                 : "+f"(c[0]), "+f"(c[1]), "+f"(c[2]), "+f"(c[3])
                 : "r"(a[0]), "r"(a[1]), "r"(a[2]), "r"(a[3]), "r"(b[0]), "r"(b[1]));
}

// MODE 0: emit Ch = fp16(acc + p0[n])
// MODE 1: emit C fp32 = (acc - p2[n])*rsqrt(p3[n]+eps)*p0[n] + p1[n]
template <int MODE, int PASSES>
__global__ __launch_bounds__(256, 2)
void mma_gemm_kernel(const __half* __restrict__ Ah,
                     const __half* __restrict__ Bhi, const __half* __restrict__ Blo,
                     float* __restrict__ C, __half* __restrict__ Ch,
                     int M, int N, int K,
                     const float* __restrict__ p0, const float* __restrict__ p1,
                     const float* __restrict__ p2, const float* __restrict__ p3) {
    constexpr int NMAT = PASSES + 1;              // matrices per stage (A, Bhi[, Blo])
    constexpr uint32_t STAGE_B = NMAT * MAT_BYTES;

    extern __shared__ __align__(16) unsigned char smem_raw[];
    uint32_t sbase = (uint32_t)__cvta_generic_to_shared(smem_raw);

    const int t = threadIdx.x;
    const int lane = t & 31;
    const int warp = t >> 5;
    const int wy = warp >> 2;       // 0..1 (M)
    const int wx = warp & 3;        // 0..3 (N)
    const int m0 = blockIdx.y * BM;
    const int n0 = blockIdx.x * BN;

    float acc[4][4][4];
    #pragma unroll
    for (int i = 0; i < 4; i++)
        #pragma unroll
        for (int j = 0; j < 4; j++)
            #pragma unroll
            for (int q = 0; q < 4; q++) acc[i][j][q] = 0.f;

    const __half* msrc[NMAT];
    msrc[0] = Ah;
    msrc[1] = Bhi;
    if (PASSES == 2) msrc[2] = Blo;

    // loader: 512 16B-chunks per 128x32 matrix; chunk c: row=c>>2, seg=c&3
    auto issue = [&](int chunk, int buf) {
        uint32_t sb = sbase + buf * STAGE_B;
        int kpos = chunk * BKK;
        #pragma unroll
        for (int i = 0; i < NMAT * 2; i++) {
            int mat = i >> 1;
            int c = (i & 1) * 256 + t;              // 0..511
            int row = c >> 2, seg = c & 3;
            uint32_t so = (uint32_t)(row * SSTRIDE + seg * 8) * 2 + (uint32_t)mat * MAT_BYTES;
            bool isA = (mat == 0);
            size_t g = (size_t)((isA ? m0 : n0) + row) * K + kpos + seg * 8;
            cp16(sb + so, msrc[mat] + g);
        }
        asm volatile("cp.async.commit_group;\n");
    };

    const uint32_t aOff = (uint32_t)((wy * 64 + (lane & 15)) * SSTRIDE + ((lane >> 4) * 8)) * 2;
    const uint32_t bOff = (uint32_t)((wx * 32 + ((lane >> 4) * 8) + (lane & 7)) * SSTRIDE
                                     + (((lane >> 3) & 1) * 8)) * 2;

    const int NK = K / BKK;
    issue(0, 0);

    for (int kt = 0; kt < NK; kt++) {
        if (kt + 1 < NK) {
            issue(kt + 1, (kt + 1) & 1);
            asm volatile("cp.async.wait_group 1;\n" ::: "memory");
        } else {
            asm volatile("cp.async.wait_group 0;\n" ::: "memory");
        }
        __syncthreads();
        uint32_t sb = sbase + (kt & 1) * STAGE_B;
        #pragma unroll
        for (int kk = 0; kk < BKK / 16; kk++) {
            uint32_t kby = (uint32_t)(kk * 16) * 2;
            uint32_t ah[4][4], bhi[4][2], blo[4][2];
            #pragma unroll
            for (int mt = 0; mt < 4; mt++) {
                uint32_t ad = sb + aOff + kby + (uint32_t)(mt * 16 * SSTRIDE) * 2;
                ldsm_x4(ah[mt][0], ah[mt][1], ah[mt][2], ah[mt][3], ad);
            }
            #pragma unroll
            for (int p = 0; p < 2; p++) {
                uint32_t bd = sb + 1 * MAT_BYTES + bOff + kby
                              + (uint32_t)(p * 16 * SSTRIDE) * 2;
                uint32_t r0, r1, r2, r3;
                ldsm_x4(r0, r1, r2, r3, bd);
                bhi[p * 2][0] = r0; bhi[p * 2][1] = r1;
                bhi[p * 2 + 1][0] = r2; bhi[p * 2 + 1][1] = r3;
                if (PASSES == 2) {
                    ldsm_x4(r0, r1, r2, r3, bd + MAT_BYTES);
                    blo[p * 2][0] = r0; blo[p * 2][1] = r1;
                    blo[p * 2 + 1][0] = r2; blo[p * 2 + 1][1] = r3;
                }
            }
            #pragma unroll
            for (int mt = 0; mt < 4; mt++)
                #pragma unroll
                for (int nt = 0; nt < 4; nt++) {
                    mma16816(acc[mt][nt], ah[mt], bhi[nt]);
                    if (PASSES == 2) mma16816(acc[mt][nt], ah[mt], blo[nt]);
                }
        }
        __syncthreads();
    }

    // epilogue
    #pragma unroll
    for (int mt = 0; mt < 4; mt++) {
        int r = m0 + wy * 64 + mt * 16 + (lane >> 2);
        #pragma unroll
        for (int nt = 0; nt < 4; nt++) {
            int c = n0 + wx * 32 + nt * 8 + (lane & 3) * 2;
            float v00 = acc[mt][nt][0], v01 = acc[mt][nt][1];
            float v10 = acc[mt][nt][2], v11 = acc[mt][nt][3];
            if (MODE == 0) {
                float b0 = p0[c], b1 = p0[c + 1];
                v00 += b0; v01 += b1; v10 += b0; v11 += b1;
                __half2 hh;
                hh.x = __float2half_rn(v00); hh.y = __float2half_rn(v01);
                *(__half2*)&Ch[(size_t)r * N + c] = hh;
                hh.x = __float2half_rn(v10); hh.y = __float2half_rn(v11);
                *(__half2*)&Ch[(size_t)(r + 8) * N + c] = hh;
            } else {
                float s0 = rsqrtf(p3[c] + BN_EPS) * p0[c];
                float s1 = rsqrtf(p3[c + 1] + BN_EPS) * p0[c + 1];
                float t0 = p1[c] - p2[c] * s0;
                float t1 = p1[c + 1] - p2[c + 1] * s1;
                float2 o0 = {v00 * s0 + t0, v01 * s1 + t1};
                float2 o1 = {v10 * s0 + t0, v11 * s1 + t1};
                *(float2*)&C[(size_t)r * N + c] = o0;
                *(float2*)&C[(size_t)(r + 8) * N + c] = o1;
            }
        }
    }
}

// ---------------- K3: attention = sigmoid(h @ fc2_w^T + b) ----------------
__global__ void att_kernel(const __half* __restrict__ hh,
                           const float* __restrict__ w2,
                           const float* __restrict__ b2, float* __restrict__ att) {
    int m = blockIdx.x;
    int warp = threadIdx.x >> 5, lane = threadIdx.x & 31;
    const __half* hr = hh + (size_t)m * ED_;
    const float* wr = w2 + (size_t)warp * ED_;
    float s = 0.f;
    for (int k = lane * 2; k < ED_; k += 64) {
        float2 a = __half22float2(*(const __half2*)&hr[k]);
        float2 w = *(const float2*)&wr[k];
        s += a.x * w.x + a.y * w.y;
    }
    for (int o = 16; o; o >>= 1) s += __shfl_xor_sync(0xffffffffu, s, o);
    if (lane == 0) {
        float v = s + b2[warp];
        att[m * G_ + warp] = 1.f / (1.f + expf(-v));
    }
}

// ---------------- K6: softmax over K within each group, times attention ----------------
__global__ void softmax_att_kernel(const float* __restrict__ act, const float* __restrict__ att,
                                   float* __restrict__ actn) {
    int m = blockIdx.x;
    int g = threadIdx.x >> 5, lane = threadIdx.x & 31;
    const float* row = act + (size_t)m * (G_ * K_) + g * K_;
    float v0 = row[lane], v1 = row[lane + 32];
    float mx = fmaxf(v0, v1);
    for (int o = 16; o; o >>= 1) mx = fmaxf(mx, __shfl_xor_sync(0xffffffffu, mx, o));
    float e0 = expf(v0 - mx), e1 = expf(v1 - mx);
    float s = e0 + e1;
    for (int o = 16; o; o >>= 1) s += __shfl_xor_sync(0xffffffffu, s, o);
    float scl = att[m * G_ + g] / s;
    float* orow = actn + (size_t)m * (G_ * K_) + g * K_;
    orow[lane] = e0 * scl;
    orow[lane + 32] = e1 * scl;
}

// ---------------- K7: asum[b,k] ----------------
__global__ void asum_kernel(const float* __restrict__ actn, float* __restrict__ asum) {
    int b = blockIdx.x;
    int t = threadIdx.x;
    int k = t & 63, grp = t >> 6;
    float s = 0.f;
    for (int n = grp; n < N2_; n += 4) {
        int row = b * FR_ + (n >> 3);
        s += actn[(size_t)row * (G_ * K_) + (n & 7) * K_ + k];
    }
    __shared__ float red[256];
    red[t] = s;
    __syncthreads();
    if (grp == 0) {
        float tot = red[k] + red[64 + k] + red[128 + k] + red[192 + k];
        asum[b * K_ + k] = tot;
    }
}

// ---------------- K8: batched VLAD GEMM ----------------
__global__ void vlad_gemm_kernel(const __half* __restrict__ hh,
                                 const float* __restrict__ actn,
                                 const float* __restrict__ asum, const float* __restrict__ c2,
                                 float* __restrict__ vlad) {
    int b  = blockIdx.x;
    int f0 = blockIdx.y * 64;
    __shared__ float Rs[32][68];
    __shared__ float Qs[32][68];
    int t = threadIdx.x;
    int tx = t & 15, ty = t >> 4;
    float acc[4][4];
    #pragma unroll
    for (int i = 0; i < 4; i++)
        #pragma unroll
        for (int j = 0; j < 4; j++) acc[i][j] = 0.f;

    for (int n0 = 0; n0 < N2_; n0 += 32) {
        __syncthreads();
        #pragma unroll
        for (int i = 0; i < 4; i++) {           // Rs: half2 pairs
            int idx = t + i * 256;
            int n = idx >> 5, fp = idx & 31;
            int f = fp * 2;
            int nn = n0 + n;
            int row = b * FR_ + (nn >> 3);
            size_t hidx = (size_t)row * ED_ + (nn & 7) * FEAT_ + f0 + f;
            float2 hv = __half22float2(*(const __half2*)&hh[hidx]);
            Rs[n][f]     = hv.x;
            Rs[n][f + 1] = hv.y;
        }
        #pragma unroll
        for (int i = 0; i < 8; i++) {           // Qs: fp32
            int idx = t + i * 256;
            int n = idx >> 6, f = idx & 63;
            int nn = n0 + n;
            int row = b * FR_ + (nn >> 3);
            Qs[n][f] = actn[(size_t)row * (G_ * K_) + (nn & 7) * K_ + f];
        }
        __syncthreads();
        #pragma unroll
        for (int nn = 0; nn < 32; nn++) {
            float rf[4], qf[4];
            *(float4*)rf = *(const float4*)&Rs[nn][ty * 4];
            *(float4*)qf = *(const float4*)&Qs[nn][tx * 4];
            #pragma unroll
            for (int i = 0; i < 4; i++)
                #pragma unroll
                for (int j = 0; j < 4; j++) acc[i][j] += rf[i] * qf[j];
        }
    }
    #pragma unroll
    for (int i = 0; i < 4; i++) {
        int f = f0 + ty * 4 + i;
        #pragma unroll
        for (int j = 0; j < 4; j++) {
            int k = tx * 4 + j;
            float v = acc[i][j] - asum[b * K_ + k] * c2[(size_t)f * K_ + k];
            vlad[((size_t)b * FEAT_ + f) * K_ + k] = v;
        }
    }
}

// ---------------- K9: intra-norm + BN2 ----------------
__global__ void intranorm_bn_kernel(const float* __restrict__ vlad, float* __restrict__ vladn,
                                    const float* __restrict__ g, const float* __restrict__ bb,
                                    const float* __restrict__ mm, const float* __restrict__ vv) {
    int b = blockIdx.x;
    int t = threadIdx.x;
    int k = t & 63, fg = t >> 6;
    float s = 0.f;
    for (int f = fg; f < FEAT_; f += 8) {
        float x = vlad[((size_t)b * FEAT_ + f) * K_ + k];
        s += x * x;
    }
    __shared__ float red[512];
    red[t] = s;
    __syncthreads();
    if (fg == 0) {
        float tot = 0.f;
        #pragma unroll
        for (int i = 0; i < 8; i++) tot += red[i * 64 + k];
        red[k] = 1.f / fmaxf(sqrtf(tot), L2_EPS);
    }
    __syncthreads();
    float inv = red[k];
    for (int f = fg; f < FEAT_; f += 8) {
        int idx = f * K_ + k;
        float x = vlad[((size_t)b * FEAT_ + f) * K_ + k] * inv;
        vladn[(size_t)b * VLAD_ + idx] =
            (x - mm[idx]) * rsqrtf(vv[idx] + BN_EPS) * g[idx] + bb[idx];
    }
}

// ---------------- K10: broadcast bias init ----------------
__global__ void bias_init_kernel(float* __restrict__ C, const float* __restrict__ bias,
                                 int rows, int N) {
    int idx = blockIdx.x * blockDim.x + threadIdx.x;
    if (idx < rows * N) C[idx] = bias[idx % N];
}

// ---------------- K11: skinny GEMM (split-K, atomic) ----------------
__global__ void skinny32_kernel(const float* __restrict__ A, const float* __restrict__ W,
                                float* __restrict__ C, int N, int K, int KC) {
    int o0 = blockIdx.x * 128;
    int k0 = blockIdx.y * KC;
    __shared__ float As[32][36];
    __shared__ float Ws[32][132];
    int t = threadIdx.x;
    int kl = t & 31, rg = t >> 5;
    int oq = t & 31, bq = t >> 5;
    float acc[4][4];
    #pragma unroll
    for (int i = 0; i < 4; i++)
        #pragma unroll
        for (int j = 0; j < 4; j++) acc[i][j] = 0.f;

    int kend = min(k0 + KC, K);
    for (int kt = k0; kt < kend; kt += 32) {
        __syncthreads();
        #pragma unroll
        for (int i = 0; i < 4; i++) {
            int b = rg + i * 8;
            As[kl][b] = A[(size_t)b * K + kt + kl];
        }
        #pragma unroll
        for (int i = 0; i < 16; i++) {
            int o = rg + i * 8;
            int og = o0 + o;
            Ws[kl][o] = (og < N) ? W[(size_t)og * K + kt + kl] : 0.f;
        }
        __syncthreads();
        #pragma unroll
        for (int kk = 0; kk < 32; kk++) {
            float4 w4 = *(const float4*)&Ws[kk][oq * 4];
            float4 a4 = *(const float4*)&As[kk][bq * 4];
            float av[4] = {a4.x, a4.y, a4.z, a4.w};
            float wv[4] = {w4.x, w4.y, w4.z, w4.w};
            #pragma unroll
            for (int i = 0; i < 4; i++)
                #pragma unroll
                for (int j = 0; j < 4; j++) acc[i][j] += av[i] * wv[j];
        }
    }
    #pragma unroll
    for (int i = 0; i < 4; i++) {
        int b = bq * 4 + i;
        #pragma unroll
        for (int j = 0; j < 4; j++) {
            int o = o0 + oq * 4 + j;
            if (o < N) atomicAdd(&C[(size_t)b * N + o], acc[i][j]);
        }
    }
}

// ---------------- K12: BN ----------------
__global__ void bn_kernel(const float* __restrict__ in, float* __restrict__ out,
                          const float* __restrict__ g, const float* __restrict__ bb,
                          const float* __restrict__ mm, const float* __restrict__ vv,
                          int rows, int N) {
    int idx = blockIdx.x * blockDim.x + threadIdx.x;
    if (idx < rows * N) {
        int c = idx % N;
        out[idx] = (in[idx] - mm[c]) * rsqrtf(vv[c] + BN_EPS) * g[c] + bb[c];
    }
}

// ---------------- K13/K14: SE gating ----------------
__global__ void se1_kernel(const float* __restrict__ y, const float* __restrict__ w,
                           const float* __restrict__ bias,
                           const float* __restrict__ g, const float* __restrict__ bb,
                           const float* __restrict__ mm, const float* __restrict__ vv,
                           float* __restrict__ z) {
    int warp = threadIdx.x >> 5, lane = threadIdx.x & 31;
    int idx = blockIdx.x * 8 + warp;
    int b = idx / HR_, o = idx % HR_;
    const float* yr = y + (size_t)b * H_;
    const float* wr = w + (size_t)o * H_;
    float s = 0.f;
    for (int k = lane; k < H_; k += 32) s += yr[k] * wr[k];
    for (int off = 16; off; off >>= 1) s += __shfl_xor_sync(0xffffffffu, s, off);
    if (lane == 0) {
        float v = s + bias[o];
        v = (v - mm[o]) * rsqrtf(vv[o] + BN_EPS) * g[o] + bb[o];
        z[(size_t)b * HR_ + o] = fmaxf(v, 0.f);
    }
}

__global__ void se2_kernel(const float* __restrict__ z, const float* __restrict__ w,
                           const float* __restrict__ bias, const float* __restrict__ y,
                           float* __restrict__ yg) {
    int warp = threadIdx.x >> 5, lane = threadIdx.x & 31;
    int idx = blockIdx.x * 8 + warp;
    int b = idx / H_, o = idx % H_;
    const float* zr = z + (size_t)b * HR_;
    const float* wr = w + (size_t)o * HR_;
    float s = 0.f;
    for (int k = lane; k < HR_; k += 32) s += zr[k] * wr[k];
    for (int off = 16; off; off >>= 1) s += __shfl_xor_sync(0xffffffffu, s, off);
    if (lane == 0) {
        float gate = 1.f / (1.f + expf(-(s + bias[o])));
        yg[(size_t)b * H_ + o] = y[(size_t)b * H_ + o] * gate;
    }
}

// ---------------- host launcher ----------------
extern "C" void kernel_launch(void* const* d_in, const int* in_sizes, int n_in,
                              void* d_out, int out_size) {
    const float* x     = (const float*)d_in[0];
    const float* fc1_w = (const float*)d_in[1];
    const float* fc1_b = (const float*)d_in[2];
    const float* fc2_w = (const float*)d_in[3];
    const float* fc2_b = (const float*)d_in[4];
    const float* c1    = (const float*)d_in[5];
    const float* c2    = (const float*)d_in[6];
    const float* bn1_g = (const float*)d_in[7];
    const float* bn1_b = (const float*)d_in[8];
    const float* bn1_m = (const float*)d_in[9];
    const float* bn1_v = (const float*)d_in[10];
    const float* bn2_g = (const float*)d_in[11];
    const float* bn2_b = (const float*)d_in[12];
    const float* bn2_m = (const float*)d_in[13];
    const float* bn2_v = (const float*)d_in[14];
    const float* cgf_w = (const float*)d_in[15];
    const float* cgf_b = (const float*)d_in[16];
    const float* cgbn_g = (const float*)d_in[17];
    const float* cgbn_b = (const float*)d_in[18];
    const float* cgbn_m = (const float*)d_in[19];
    const float* cgbn_v = (const float*)d_in[20];
    const float* g1_w  = (const float*)d_in[21];
    const float* g1_b  = (const float*)d_in[22];
    const float* gbn_g = (const float*)d_in[23];
    const float* gbn_b = (const float*)d_in[24];
    const float* gbn_m = (const float*)d_in[25];
    const float* gbn_v = (const float*)d_in[26];
    const float* g2_w  = (const float*)d_in[27];
    const float* g2_b  = (const float*)d_in[28];
    const float* fc3_w = (const float*)d_in[29];
    const float* fc3_b = (const float*)d_in[30];
    float* out = (float*)d_out;

    float *rinv, *att, *act, *actn, *asum, *vlad, *vladn, *y0, *y, *z, *yg;
    __half *xh, *wh, *hh, *c1h, *c1l;
    cudaGetSymbolAddress((void**)&rinv,  g_rinv);
    cudaGetSymbolAddress((void**)&att,   g_att);
    cudaGetSymbolAddress((void**)&act,   g_act);
    cudaGetSymbolAddress((void**)&actn,  g_actn);
    cudaGetSymbolAddress((void**)&asum,  g_asum);
    cudaGetSymbolAddress((void**)&vlad,  g_vlad);
    cudaGetSymbolAddress((void**)&vladn, g_vladn);
    cudaGetSymbolAddress((void**)&y0,    g_y0);
    cudaGetSymbolAddress((void**)&y,     g_y);
    cudaGetSymbolAddress((void**)&z,     g_z);
    cudaGetSymbolAddress((void**)&yg,    g_yg);
    cudaGetSymbolAddress((void**)&xh,    g_xh);
    cudaGetSymbolAddress((void**)&wh,    g_wh);
    cudaGetSymbolAddress((void**)&hh,    g_hh);
    cudaGetSymbolAddress((void**)&c1h,   g_c1h);
    cudaGetSymbolAddress((void**)&c1l,   g_c1l);

    const int SMEM1 = 2 * 2 * MAT_BYTES;   // PASSES=1: 40960
    const int SMEM2 = 2 * 3 * MAT_BYTES;   // PASSES=2: 61440
    cudaFuncSetAttribute((const void*)mma_gemm_kernel<0, 1>,
                         cudaFuncAttributeMaxDynamicSharedMemorySize, SMEM1);
    cudaFuncSetAttribute((const void*)mma_gemm_kernel<1, 2>,
                         cudaFuncAttributeMaxDynamicSharedMemorySize, SMEM2);

    // 1. row inverse norms of x
    rownorm_inv_kernel<<<M_, 256>>>(x, rinv);

    // 2. x -> fp16 (scaled); fc1_w -> fp16
    tohalf_kernel<<<(M_ * D_ / 4 + 255) / 256, 256>>>(x, xh, M_ * D_, rinv, D_);
    tohalf_kernel<<<(ED_ * D_ / 4 + 255) / 256, 256>>>(fc1_w, wh, ED_ * D_, nullptr, 0);

    // 3. h (fp16) = xn @ fc1_w^T + fc1_b — 1-pass fp16 tensor cores
    mma_gemm_kernel<0, 1><<<dim3(ED_ / BN, M_ / BM), 256, SMEM1>>>(
        xh, wh, nullptr, nullptr, hh, M_, ED_, D_, fc1_b, nullptr, nullptr, nullptr);

    // 4. attention
    att_kernel<<<M_, 256>>>(hh, fc2_w, fc2_b, att);

    // 5. c1^T + fp16 split, fused
    transpose_split_kernel<<<dim3((G_ * K_) / 32, ED_ / 32), 256>>>(c1, c1h, c1l, ED_, G_ * K_);

    // 6. act = BN1(h @ c1) — 2-pass fp16 tensor cores
    mma_gemm_kernel<1, 2><<<dim3((G_ * K_) / BN, M_ / BM), 256, SMEM2>>>(
        hh, c1h, c1l, act, nullptr, M_, G_ * K_, ED_,
        bn1_g, bn1_b, bn1_m, bn1_v);

    // 7. softmax * att
    softmax_att_kernel<<<M_, 256>>>(act, att, actn);

    // 8. asum
    asum_kernel<<<B_, 256>>>(actn, asum);

    // 9. vlad
    vlad_gemm_kernel<<<dim3(B_, FEAT_ / 64), 256>>>(hh, actn, asum, c2, vlad);

    // 10. intra-norm + BN2
    intranorm_bn_kernel<<<B_, 512>>>(vlad, vladn, bn2_g, bn2_b, bn2_m, bn2_v);

    // 11. y = BN(vladn @ cgf_w^T + cgf_b)
    bias_init_kernel<<<(B_ * H_ + 255) / 256, 256>>>(y0, cgf_b, B_, H_);
    skinny32_kernel<<<dim3(H_ / 128, 16), 256>>>(vladn, cgf_w, y0, H_, VLAD_, VLAD_ / 16);
    bn_kernel<<<(B_ * H_ + 255) / 256, 256>>>(y0, y, cgbn_g, cgbn_b, cgbn_m, cgbn_v, B_, H_);

    // 12. SE gating
    se1_kernel<<<(B_ * HR_) / 8, 256>>>(y, g1_w, g1_b, gbn_g, gbn_b, gbn_m, gbn_v, z);
    se2_kernel<<<(B_ * H_) / 8, 256>>>(z, g2_w, g2_b, y, yg);

    // 13. out = yg @ fc3_w^T + fc3_b
    bias_init_kernel<<<(B_ * NC_ + 255) / 256, 256>>>(out, fc3_b, B_, NC_);
    skinny32_kernel<<<dim3((NC_ + 127) / 128, 8), 256>>>(yg, fc3_w, out, NC_, H_, H_ / 8);
}

// round 10
// speedup vs baseline: 2.0094x; 1.1717x over previous
#include <cuda_runtime.h>
#include <cuda_fp16.h>
#include <math.h>
#include <stdint.h>

// ---------------- problem constants ----------------
#define B_    32
#define FR_   300
#define D_    2048
#define ED_   4096      // E*D
#define G_    8
#define K_    64
#define FEAT_ 512       // E*D/G
#define VLAD_ 32768     // K*FEAT
#define H_    2048
#define HR_   256       // H/R
#define NC_   3862
#define M_    (B_*FR_)  // 9600
#define N2_   2400      // FR*G
#define BN_EPS 1e-5f
#define L2_EPS 1e-12f

// ---------------- scratch (device globals; no allocs allowed) ----------------
__device__ __align__(128) float g_rinv[M_];
__device__ __align__(128) float g_att[M_ * G_];
__device__ __align__(128) float g_act[M_ * (G_*K_)];
__device__ __align__(128) float g_actn[M_ * (G_*K_)];
__device__ __align__(128) float g_asum[B_ * K_];
__device__ __align__(128) float g_vlad[B_ * FEAT_ * K_];
__device__ __align__(128) float g_vladn[B_ * VLAD_];
__device__ __align__(128) float g_y0[B_ * H_];
__device__ __align__(128) float g_y[B_ * H_];
__device__ __align__(128) float g_z[B_ * HR_];
__device__ __align__(128) float g_yg[B_ * H_];
// fp16 buffers
__device__ __align__(128) __half g_xh[M_ * D_];
__device__ __align__(128) __half g_wh[ED_ * D_];
__device__ __align__(128) __half g_hh[M_ * ED_];
__device__ __align__(128) __half g_c1h[(G_*K_) * ED_];

// ---------------- K1: per-row inverse L2 norm of x ----------------
__global__ void rownorm_inv_kernel(const float* __restrict__ x, float* __restrict__ rinv) {
    int m = blockIdx.x;
    int t = threadIdx.x;
    float s = 0.f;
    const float* row = x + (size_t)m * D_;
    for (int k = t; k < D_; k += 256) { float v = row[k]; s += v * v; }
    for (int o = 16; o; o >>= 1) s += __shfl_xor_sync(0xffffffffu, s, o);
    __shared__ float red[8];
    if ((t & 31) == 0) red[t >> 5] = s;
    __syncthreads();
    if (t == 0) {
        float tot = 0.f;
        #pragma unroll
        for (int i = 0; i < 8; i++) tot += red[i];
        rinv[m] = 1.f / fmaxf(sqrtf(tot), L2_EPS);
    }
}

// ---------------- K2: fp32 -> fp16, optional row scale ----------------
__global__ void tohalf_kernel(const float* __restrict__ src, __half* __restrict__ dst,
                              int n, const float* __restrict__ rowscale, int rowlen) {
    int i = (blockIdx.x * blockDim.x + threadIdx.x) * 4;
    if (i >= n) return;
    float4 v = *(const float4*)(src + i);
    if (rowscale) {
        float s = rowscale[i / rowlen];
        v.x *= s; v.y *= s; v.z *= s; v.w *= s;
    }
    __half2 a; a.x = __float2half_rn(v.x); a.y = __float2half_rn(v.y);
    __half2 b; b.x = __float2half_rn(v.z); b.y = __float2half_rn(v.w);
    *(__half2*)&dst[i]     = a;
    *(__half2*)&dst[i + 2] = b;
}

// ---------------- K2b: fused transpose -> fp16: c1[R,C] -> c1h[C,R] ----------------
__global__ void transpose_half_kernel(const float* __restrict__ in,
                                      __half* __restrict__ outh, int R, int C) {
    __shared__ float tile[32][33];
    int c0 = blockIdx.x * 32, r0 = blockIdx.y * 32;
    int tx = threadIdx.x & 31, ty = threadIdx.x >> 5;   // 256 thr
    #pragma unroll
    for (int i = 0; i < 32; i += 8)
        tile[ty + i][tx] = in[(size_t)(r0 + ty + i) * C + c0 + tx];
    __syncthreads();
    #pragma unroll
    for (int i = 0; i < 32; i += 8) {
        float v = tile[tx][ty + i];
        outh[(size_t)(c0 + ty + i) * R + r0 + tx] = __float2half_rn(v);
    }
}

// ---------------- tensor-core GEMM: C[M,N] = A[M,K] * B[N,K]^T  (fp16 1-pass) ---------
// BK=64, 2 stages, 72KB smem, 2 CTAs/SM.
#define BM 128
#define BN 128
#define BKK 64
#define SSTRIDE 72                        // BKK + 8
#define MAT_BYTES (128 * SSTRIDE * 2)     // 18432
#define STAGE_B (2 * MAT_BYTES)           // 36864
#define GEMM_SMEM (2 * STAGE_B)           // 73728

__device__ __forceinline__ void cp16(uint32_t dst, const void* src) {
    asm volatile("cp.async.cg.shared.global [%0], [%1], 16;\n" :: "r"(dst), "l"(src));
}
__device__ __forceinline__ void ldsm_x4(uint32_t& r0, uint32_t& r1, uint32_t& r2, uint32_t& r3,
                                        uint32_t addr) {
    asm volatile("ldmatrix.sync.aligned.m8n8.x4.shared.b16 {%0,%1,%2,%3}, [%4];\n"
                 : "=r"(r0), "=r"(r1), "=r"(r2), "=r"(r3) : "r"(addr));
}
__device__ __forceinline__ void mma16816(float* c, const uint32_t* a, const uint32_t* b) {
    asm volatile("mma.sync.aligned.m16n8k16.row.col.f32.f16.f16.f32 "
                 "{%0,%1,%2,%3},{%4,%5,%6,%7},{%8,%9},{%0,%1,%2,%3};\n"
                 : "+f"(c[0]), "+f"(c[1]), "+f"(c[2]), "+f"(c[3])
                 : "r"(a[0]), "r"(a[1]), "r"(a[2]), "r"(a[3]), "r"(b[0]), "r"(b[1]));
}

// MODE 0: emit Ch = fp16(acc + p0[n])
// MODE 1: emit C fp32 = (acc - p2[n])*rsqrt(p3[n]+eps)*p0[n] + p1[n]
template <int MODE>
__global__ __launch_bounds__(256, 2)
void mma_gemm_kernel(const __half* __restrict__ Ah, const __half* __restrict__ Bh,
                     float* __restrict__ C, __half* __restrict__ Ch,
                     int M, int N, int K,
                     const float* __restrict__ p0, const float* __restrict__ p1,
                     const float* __restrict__ p2, const float* __restrict__ p3) {
    extern __shared__ __align__(16) unsigned char smem_raw[];
    uint32_t sbase = (uint32_t)__cvta_generic_to_shared(smem_raw);

    const int t = threadIdx.x;
    const int lane = t & 31;
    const int warp = t >> 5;
    const int wy = warp >> 2;       // 0..1 (M)
    const int wx = warp & 3;        // 0..3 (N)
    const int m0 = blockIdx.y * BM;
    const int n0 = blockIdx.x * BN;

    float acc[4][4][4];
    #pragma unroll
    for (int i = 0; i < 4; i++)
        #pragma unroll
        for (int j = 0; j < 4; j++)
            #pragma unroll
            for (int q = 0; q < 4; q++) acc[i][j][q] = 0.f;

    // loader: 1024 16B-chunks per 128x64 matrix; 4 per thread per matrix
    auto issue = [&](int chunk, int buf) {
        uint32_t sb = sbase + buf * STAGE_B;
        int kpos = chunk * BKK;
        #pragma unroll
        for (int i = 0; i < 4; i++) {
            int c = t + i * 256;
            int row = c >> 3, seg = c & 7;
            uint32_t so = (uint32_t)(row * SSTRIDE + seg * 8) * 2;
            cp16(sb + so, Ah + (size_t)(m0 + row) * K + kpos + seg * 8);
            cp16(sb + MAT_BYTES + so, Bh + (size_t)(n0 + row) * K + kpos + seg * 8);
        }
        asm volatile("cp.async.commit_group;\n");
    };

    const uint32_t aOff = (uint32_t)((wy * 64 + (lane & 15)) * SSTRIDE + ((lane >> 4) * 8)) * 2;
    const uint32_t bOff = (uint32_t)((wx * 32 + ((lane >> 4) * 8) + (lane & 7)) * SSTRIDE
                                     + (((lane >> 3) & 1) * 8)) * 2;

    const int NK = K / BKK;
    issue(0, 0);

    for (int kt = 0; kt < NK; kt++) {
        if (kt + 1 < NK) {
            issue(kt + 1, (kt + 1) & 1);
            asm volatile("cp.async.wait_group 1;\n" ::: "memory");
        } else {
            asm volatile("cp.async.wait_group 0;\n" ::: "memory");
        }
        __syncthreads();
        uint32_t sb = sbase + (kt & 1) * STAGE_B;
        #pragma unroll
        for (int kk = 0; kk < BKK / 16; kk++) {
            uint32_t kby = (uint32_t)(kk * 16) * 2;
            uint32_t ah[4][4], bh[4][2];
            #pragma unroll
            for (int mt = 0; mt < 4; mt++) {
                uint32_t ad = sb + aOff + kby + (uint32_t)(mt * 16 * SSTRIDE) * 2;
                ldsm_x4(ah[mt][0], ah[mt][1], ah[mt][2], ah[mt][3], ad);
            }
            #pragma unroll
            for (int p = 0; p < 2; p++) {
                uint32_t bd = sb + MAT_BYTES + bOff + kby + (uint32_t)(p * 16 * SSTRIDE) * 2;
                uint32_t r0, r1, r2, r3;
                ldsm_x4(r0, r1, r2, r3, bd);
                bh[p * 2][0] = r0; bh[p * 2][1] = r1;
                bh[p * 2 + 1][0] = r2; bh[p * 2 + 1][1] = r3;
            }
            #pragma unroll
            for (int mt = 0; mt < 4; mt++)
                #pragma unroll
                for (int nt = 0; nt < 4; nt++)
                    mma16816(acc[mt][nt], ah[mt], bh[nt]);
        }
        __syncthreads();
    }

    // epilogue
    #pragma unroll
    for (int mt = 0; mt < 4; mt++) {
        int r = m0 + wy * 64 + mt * 16 + (lane >> 2);
        #pragma unroll
        for (int nt = 0; nt < 4; nt++) {
            int c = n0 + wx * 32 + nt * 8 + (lane & 3) * 2;
            float v00 = acc[mt][nt][0], v01 = acc[mt][nt][1];
            float v10 = acc[mt][nt][2], v11 = acc[mt][nt][3];
            if (MODE == 0) {
                float b0 = p0[c], b1 = p0[c + 1];
                v00 += b0; v01 += b1; v10 += b0; v11 += b1;
                __half2 hh;
                hh.x = __float2half_rn(v00); hh.y = __float2half_rn(v01);
                *(__half2*)&Ch[(size_t)r * N + c] = hh;
                hh.x = __float2half_rn(v10); hh.y = __float2half_rn(v11);
                *(__half2*)&Ch[(size_t)(r + 8) * N + c] = hh;
            } else {
                float s0 = rsqrtf(p3[c] + BN_EPS) * p0[c];
                float s1 = rsqrtf(p3[c + 1] + BN_EPS) * p0[c + 1];
                float t0 = p1[c] - p2[c] * s0;
                float t1 = p1[c + 1] - p2[c + 1] * s1;
                float2 o0 = {v00 * s0 + t0, v01 * s1 + t1};
                float2 o1 = {v10 * s0 + t0, v11 * s1 + t1};
                *(float2*)&C[(size_t)r * N + c] = o0;
                *(float2*)&C[(size_t)(r + 8) * N + c] = o1;
            }
        }
    }
}

// ---------------- K3: attention = sigmoid(h @ fc2_w^T + b) ----------------
__global__ void att_kernel(const __half* __restrict__ hh,
                           const float* __restrict__ w2,
                           const float* __restrict__ b2, float* __restrict__ att) {
    int m = blockIdx.x;
    int warp = threadIdx.x >> 5, lane = threadIdx.x & 31;
    const __half* hr = hh + (size_t)m * ED_;
    const float* wr = w2 + (size_t)warp * ED_;
    float s = 0.f;
    for (int k = lane * 2; k < ED_; k += 64) {
        float2 a = __half22float2(*(const __half2*)&hr[k]);
        float2 w = *(const float2*)&wr[k];
        s += a.x * w.x + a.y * w.y;
    }
    for (int o = 16; o; o >>= 1) s += __shfl_xor_sync(0xffffffffu, s, o);
    if (lane == 0) {
        float v = s + b2[warp];
        att[m * G_ + warp] = 1.f / (1.f + expf(-v));
    }
}

// ---------------- K6: softmax over K within each group, times attention ----------------
__global__ void softmax_att_kernel(const float* __restrict__ act, const float* __restrict__ att,
                                   float* __restrict__ actn) {
    int m = blockIdx.x;
    int g = threadIdx.x >> 5, lane = threadIdx.x & 31;
    const float* row = act + (size_t)m * (G_ * K_) + g * K_;
    float v0 = row[lane], v1 = row[lane + 32];
    float mx = fmaxf(v0, v1);
    for (int o = 16; o; o >>= 1) mx = fmaxf(mx, __shfl_xor_sync(0xffffffffu, mx, o));
    float e0 = expf(v0 - mx), e1 = expf(v1 - mx);
    float s = e0 + e1;
    for (int o = 16; o; o >>= 1) s += __shfl_xor_sync(0xffffffffu, s, o);
    float scl = att[m * G_ + g] / s;
    float* orow = actn + (size_t)m * (G_ * K_) + g * K_;
    orow[lane] = e0 * scl;
    orow[lane + 32] = e1 * scl;
}

// ---------------- K7: asum[b,k] ----------------
__global__ void asum_kernel(const float* __restrict__ actn, float* __restrict__ asum) {
    int b = blockIdx.x;
    int t = threadIdx.x;
    int k = t & 63, grp = t >> 6;
    float s = 0.f;
    for (int n = grp; n < N2_; n += 4) {
        int row = b * FR_ + (n >> 3);
        s += actn[(size_t)row * (G_ * K_) + (n & 7) * K_ + k];
    }
    __shared__ float red[256];
    red[t] = s;
    __syncthreads();
    if (grp == 0) {
        float tot = red[k] + red[64 + k] + red[128 + k] + red[192 + k];
        asum[b * K_ + k] = tot;
    }
}

// ---------------- K8: batched VLAD GEMM ----------------
__global__ void vlad_gemm_kernel(const __half* __restrict__ hh,
                                 const float* __restrict__ actn,
                                 const float* __restrict__ asum, const float* __restrict__ c2,
                                 float* __restrict__ vlad) {
    int b  = blockIdx.x;
    int f0 = blockIdx.y * 64;
    __shared__ float Rs[32][68];
    __shared__ float Qs[32][68];
    int t = threadIdx.x;
    int tx = t & 15, ty = t >> 4;
    float acc[4][4];
    #pragma unroll
    for (int i = 0; i < 4; i++)
        #pragma unroll
        for (int j = 0; j < 4; j++) acc[i][j] = 0.f;

    for (int n0 = 0; n0 < N2_; n0 += 32) {
        __syncthreads();
        #pragma unroll
        for (int i = 0; i < 4; i++) {           // Rs: half2 pairs
            int idx = t + i * 256;
            int n = idx >> 5, fp = idx & 31;
            int f = fp * 2;
            int nn = n0 + n;
            int row = b * FR_ + (nn >> 3);
            size_t hidx = (size_t)row * ED_ + (nn & 7) * FEAT_ + f0 + f;
            float2 hv = __half22float2(*(const __half2*)&hh[hidx]);
            Rs[n][f]     = hv.x;
            Rs[n][f + 1] = hv.y;
        }
        #pragma unroll
        for (int i = 0; i < 8; i++) {           // Qs: fp32
            int idx = t + i * 256;
            int n = idx >> 6, f = idx & 63;
            int nn = n0 + n;
            int row = b * FR_ + (nn >> 3);
            Qs[n][f] = actn[(size_t)row * (G_ * K_) + (nn & 7) * K_ + f];
        }
        __syncthreads();
        #pragma unroll
        for (int nn = 0; nn < 32; nn++) {
            float rf[4], qf[4];
            *(float4*)rf = *(const float4*)&Rs[nn][ty * 4];
            *(float4*)qf = *(const float4*)&Qs[nn][tx * 4];
            #pragma unroll
            for (int i = 0; i < 4; i++)
                #pragma unroll
                for (int j = 0; j < 4; j++) acc[i][j] += rf[i] * qf[j];
        }
    }
    #pragma unroll
    for (int i = 0; i < 4; i++) {
        int f = f0 + ty * 4 + i;
        #pragma unroll
        for (int j = 0; j < 4; j++) {
            int k = tx * 4 + j;
            float v = acc[i][j] - asum[b * K_ + k] * c2[(size_t)f * K_ + k];
            vlad[((size_t)b * FEAT_ + f) * K_ + k] = v;
        }
    }
}

// ---------------- K9: intra-norm + BN2 ----------------
__global__ void intranorm_bn_kernel(const float* __restrict__ vlad, float* __restrict__ vladn,
                                    const float* __restrict__ g, const float* __restrict__ bb,
                                    const float* __restrict__ mm, const float* __restrict__ vv) {
    int b = blockIdx.x;
    int t = threadIdx.x;
    int k = t & 63, fg = t >> 6;
    float s = 0.f;
    for (int f = fg; f < FEAT_; f += 8) {
        float x = vlad[((size_t)b * FEAT_ + f) * K_ + k];
        s += x * x;
    }
    __shared__ float red[512];
    red[t] = s;
    __syncthreads();
    if (fg == 0) {
        float tot = 0.f;
        #pragma unroll
        for (int i = 0; i < 8; i++) tot += red[i * 64 + k];
        red[k] = 1.f / fmaxf(sqrtf(tot), L2_EPS);
    }
    __syncthreads();
    float inv = red[k];
    for (int f = fg; f < FEAT_; f += 8) {
        int idx = f * K_ + k;
        float x = vlad[((size_t)b * FEAT_ + f) * K_ + k] * inv;
        vladn[(size_t)b * VLAD_ + idx] =
            (x - mm[idx]) * rsqrtf(vv[idx] + BN_EPS) * g[idx] + bb[idx];
    }
}

// ---------------- K10: broadcast bias init ----------------
__global__ void bias_init_kernel(float* __restrict__ C, const float* __restrict__ bias,
                                 int rows, int N) {
    int idx = blockIdx.x * blockDim.x + threadIdx.x;
    if (idx < rows * N) C[idx] = bias[idx % N];
}

// ---------------- K11: skinny GEMM (split-K, atomic) ----------------
__global__ void skinny32_kernel(const float* __restrict__ A, const float* __restrict__ W,
                                float* __restrict__ C, int N, int K, int KC) {
    int o0 = blockIdx.x * 128;
    int k0 = blockIdx.y * KC;
    __shared__ float As[32][36];
    __shared__ float Ws[32][132];
    int t = threadIdx.x;
    int kl = t & 31, rg = t >> 5;
    int oq = t & 31, bq = t >> 5;
    float acc[4][4];
    #pragma unroll
    for (int i = 0; i < 4; i++)
        #pragma unroll
        for (int j = 0; j < 4; j++) acc[i][j] = 0.f;

    int kend = min(k0 + KC, K);
    for (int kt = k0; kt < kend; kt += 32) {
        __syncthreads();
        #pragma unroll
        for (int i = 0; i < 4; i++) {
            int b = rg + i * 8;
            As[kl][b] = A[(size_t)b * K + kt + kl];
        }
        #pragma unroll
        for (int i = 0; i < 16; i++) {
            int o = rg + i * 8;
            int og = o0 + o;
            Ws[kl][o] = (og < N) ? W[(size_t)og * K + kt + kl] : 0.f;
        }
        __syncthreads();
        #pragma unroll
        for (int kk = 0; kk < 32; kk++) {
            float4 w4 = *(const float4*)&Ws[kk][oq * 4];
            float4 a4 = *(const float4*)&As[kk][bq * 4];
            float av[4] = {a4.x, a4.y, a4.z, a4.w};
            float wv[4] = {w4.x, w4.y, w4.z, w4.w};
            #pragma unroll
            for (int i = 0; i < 4; i++)
                #pragma unroll
                for (int j = 0; j < 4; j++) acc[i][j] += av[i] * wv[j];
        }
    }
    #pragma unroll
    for (int i = 0; i < 4; i++) {
        int b = bq * 4 + i;
        #pragma unroll
        for (int j = 0; j < 4; j++) {
            int o = o0 + oq * 4 + j;
            if (o < N) atomicAdd(&C[(size_t)b * N + o], acc[i][j]);
        }
    }
}

// ---------------- K12: BN ----------------
__global__ void bn_kernel(const float* __restrict__ in, float* __restrict__ out,
                          const float* __restrict__ g, const float* __restrict__ bb,
                          const float* __restrict__ mm, const float* __restrict__ vv,
                          int rows, int N) {
    int idx = blockIdx.x * blockDim.x + threadIdx.x;
    if (idx < rows * N) {
        int c = idx % N;
        out[idx] = (in[idx] - mm[c]) * rsqrtf(vv[c] + BN_EPS) * g[c] + bb[c];
    }
}

// ---------------- K13/K14: SE gating ----------------
__global__ void se1_kernel(const float* __restrict__ y, const float* __restrict__ w,
                           const float* __restrict__ bias,
                           const float* __restrict__ g, const float* __restrict__ bb,
                           const float* __restrict__ mm, const float* __restrict__ vv,
                           float* __restrict__ z) {
    int warp = threadIdx.x >> 5, lane = threadIdx.x & 31;
    int idx = blockIdx.x * 8 + warp;
    int b = idx / HR_, o = idx % HR_;
    const float* yr = y + (size_t)b * H_;
    const float* wr = w + (size_t)o * H_;
    float s = 0.f;
    for (int k = lane; k < H_; k += 32) s += yr[k] * wr[k];
    for (int off = 16; off; off >>= 1) s += __shfl_xor_sync(0xffffffffu, s, off);
    if (lane == 0) {
        float v = s + bias[o];
        v = (v - mm[o]) * rsqrtf(vv[o] + BN_EPS) * g[o] + bb[o];
        z[(size_t)b * HR_ + o] = fmaxf(v, 0.f);
    }
}

__global__ void se2_kernel(const float* __restrict__ z, const float* __restrict__ w,
                           const float* __restrict__ bias, const float* __restrict__ y,
                           float* __restrict__ yg) {
    int warp = threadIdx.x >> 5, lane = threadIdx.x & 31;
    int idx = blockIdx.x * 8 + warp;
    int b = idx / H_, o = idx % H_;
    const float* zr = z + (size_t)b * HR_;
    const float* wr = w + (size_t)o * HR_;
    float s = 0.f;
    for (int k = lane; k < HR_; k += 32) s += zr[k] * wr[k];
    for (int off = 16; off; off >>= 1) s += __shfl_xor_sync(0xffffffffu, s, off);
    if (lane == 0) {
        float gate = 1.f / (1.f + expf(-(s + bias[o])));
        yg[(size_t)b * H_ + o] = y[(size_t)b * H_ + o] * gate;
    }
}

// ---------------- host launcher ----------------
extern "C" void kernel_launch(void* const* d_in, const int* in_sizes, int n_in,
                              void* d_out, int out_size) {
    const float* x     = (const float*)d_in[0];
    const float* fc1_w = (const float*)d_in[1];
    const float* fc1_b = (const float*)d_in[2];
    const float* fc2_w = (const float*)d_in[3];
    const float* fc2_b = (const float*)d_in[4];
    const float* c1    = (const float*)d_in[5];
    const float* c2    = (const float*)d_in[6];
    const float* bn1_g = (const float*)d_in[7];
    const float* bn1_b = (const float*)d_in[8];
    const float* bn1_m = (const float*)d_in[9];
    const float* bn1_v = (const float*)d_in[10];
    const float* bn2_g = (const float*)d_in[11];
    const float* bn2_b = (const float*)d_in[12];
    const float* bn2_m = (const float*)d_in[13];
    const float* bn2_v = (const float*)d_in[14];
    const float* cgf_w = (const float*)d_in[15];
    const float* cgf_b = (const float*)d_in[16];
    const float* cgbn_g = (const float*)d_in[17];
    const float* cgbn_b = (const float*)d_in[18];
    const float* cgbn_m = (const float*)d_in[19];
    const float* cgbn_v = (const float*)d_in[20];
    const float* g1_w  = (const float*)d_in[21];
    const float* g1_b  = (const float*)d_in[22];
    const float* gbn_g = (const float*)d_in[23];
    const float* gbn_b = (const float*)d_in[24];
    const float* gbn_m = (const float*)d_in[25];
    const float* gbn_v = (const float*)d_in[26];
    const float* g2_w  = (const float*)d_in[27];
    const float* g2_b  = (const float*)d_in[28];
    const float* fc3_w = (const float*)d_in[29];
    const float* fc3_b = (const float*)d_in[30];
    float* out = (float*)d_out;

    float *rinv, *att, *act, *actn, *asum, *vlad, *vladn, *y0, *y, *z, *yg;
    __half *xh, *wh, *hh, *c1h;
    cudaGetSymbolAddress((void**)&rinv,  g_rinv);
    cudaGetSymbolAddress((void**)&att,   g_att);
    cudaGetSymbolAddress((void**)&act,   g_act);
    cudaGetSymbolAddress((void**)&actn,  g_actn);
    cudaGetSymbolAddress((void**)&asum,  g_asum);
    cudaGetSymbolAddress((void**)&vlad,  g_vlad);
    cudaGetSymbolAddress((void**)&vladn, g_vladn);
    cudaGetSymbolAddress((void**)&y0,    g_y0);
    cudaGetSymbolAddress((void**)&y,     g_y);
    cudaGetSymbolAddress((void**)&z,     g_z);
    cudaGetSymbolAddress((void**)&yg,    g_yg);
    cudaGetSymbolAddress((void**)&xh,    g_xh);
    cudaGetSymbolAddress((void**)&wh,    g_wh);
    cudaGetSymbolAddress((void**)&hh,    g_hh);
    cudaGetSymbolAddress((void**)&c1h,   g_c1h);

    cudaFuncSetAttribute((const void*)mma_gemm_kernel<0>,
                         cudaFuncAttributeMaxDynamicSharedMemorySize, GEMM_SMEM);
    cudaFuncSetAttribute((const void*)mma_gemm_kernel<1>,
                         cudaFuncAttributeMaxDynamicSharedMemorySize, GEMM_SMEM);

    // 1. row inverse norms of x
    rownorm_inv_kernel<<<M_, 256>>>(x, rinv);

    // 2. x -> fp16 (scaled); fc1_w -> fp16
    tohalf_kernel<<<(M_ * D_ / 4 + 255) / 256, 256>>>(x, xh, M_ * D_, rinv, D_);
    tohalf_kernel<<<(ED_ * D_ / 4 + 255) / 256, 256>>>(fc1_w, wh, ED_ * D_, nullptr, 0);

    // 3. h (fp16) = xn @ fc1_w^T + fc1_b — 1-pass fp16, BK=64
    mma_gemm_kernel<0><<<dim3(ED_ / BN, M_ / BM), 256, GEMM_SMEM>>>(
        xh, wh, nullptr, hh, M_, ED_, D_, fc1_b, nullptr, nullptr, nullptr);

    // 4. attention
    att_kernel<<<M_, 256>>>(hh, fc2_w, fc2_b, att);

    // 5. c1^T -> fp16
    transpose_half_kernel<<<dim3((G_ * K_) / 32, ED_ / 32), 256>>>(c1, c1h, ED_, G_ * K_);

    // 6. act = BN1(h @ c1) — 1-pass fp16, BK=64
    mma_gemm_kernel<1><<<dim3((G_ * K_) / BN, M_ / BM), 256, GEMM_SMEM>>>(
        hh, c1h, act, nullptr, M_, G_ * K_, ED_, bn1_g, bn1_b, bn1_m, bn1_v);

    // 7. softmax * att
    softmax_att_kernel<<<M_, 256>>>(act, att, actn);

    // 8. asum
    asum_kernel<<<B_, 256>>>(actn, asum);

    // 9. vlad
    vlad_gemm_kernel<<<dim3(B_, FEAT_ / 64), 256>>>(hh, actn, asum, c2, vlad);

    // 10. intra-norm + BN2
    intranorm_bn_kernel<<<B_, 512>>>(vlad, vladn, bn2_g, bn2_b, bn2_m, bn2_v);

    // 11. y = BN(vladn @ cgf_w^T + cgf_b) — 32-way split-K
    bias_init_kernel<<<(B_ * H_ + 255) / 256, 256>>>(y0, cgf_b, B_, H_);
    skinny32_kernel<<<dim3(H_ / 128, 32), 256>>>(vladn, cgf_w, y0, H_, VLAD_, VLAD_ / 32);
    bn_kernel<<<(B_ * H_ + 255) / 256, 256>>>(y0, y, cgbn_g, cgbn_b, cgbn_m, cgbn_v, B_, H_);

    // 12. SE gating
    se1_kernel<<<(B_ * HR_) / 8, 256>>>(y, g1_w, g1_b, gbn_g, gbn_b, gbn_m, gbn_v, z);
    se2_kernel<<<(B_ * H_) / 8, 256>>>(z, g2_w, g2_b, y, yg);

    // 13. out = yg @ fc3_w^T + fc3_b — 16-way split-K
    bias_init_kernel<<<(B_ * NC_ + 255) / 256, 256>>>(out, fc3_b, B_, NC_);
    skinny32_kernel<<<dim3((NC_ + 127) / 128, 16), 256>>>(yg, fc3_w, out, NC_, H_, H_ / 16);
}